// round 7
// baseline (speedup 1.0000x reference)
#include <cuda_runtime.h>
#include <math.h>

// Problem constants
#define HIDDEN 2048
#define NHEADS 16
#define HDIM   128
#define SEQL   2048
#define BATCHN 2
#define WINDOW 256
#define ROWS   (BATCHN * SEQL)   // 4096
#define DM     (NHEADS * HDIM)   // 2048

// -------------------- scratch (no allocations allowed) --------------------
__device__ float s_Q[ROWS * DM];
__device__ float s_K[ROWS * DM];
__device__ float s_V[ROWS * DM];
__device__ float s_att[ROWS * DM];

// ======================= SGEMM (fast, verified): C = A@W + bias ============
#define GBM 128
#define GBN 128
#define GBK 8

__global__ __launch_bounds__(256) void sgemm_bias_kernel(
    const float* __restrict__ A, const float* __restrict__ W,
    const float* __restrict__ bias, float* __restrict__ C,
    int M, int N, int K)
{
    __shared__ float As[GBK][GBM];
    __shared__ float Bs[GBK][GBN];

    const int tid = threadIdx.x;
    const int tx  = tid & 15;
    const int ty  = tid >> 4;
    const int bx  = blockIdx.x;
    const int by  = blockIdx.y;

    const float* Ablk = A + (size_t)by * GBM * K;
    const float* Wblk = W + (size_t)bx * GBN;

    const int arow = tid >> 1;
    const int acol = (tid & 1) << 2;
    const int brow = tid >> 5;
    const int bcol = (tid & 31) << 2;

    float acc[8][8];
    #pragma unroll
    for (int i = 0; i < 8; i++)
        #pragma unroll
        for (int j = 0; j < 8; j++) acc[i][j] = 0.f;

    for (int k0 = 0; k0 < K; k0 += GBK) {
        float4 a4 = *reinterpret_cast<const float4*>(Ablk + (size_t)arow * K + k0 + acol);
        As[acol + 0][arow] = a4.x;
        As[acol + 1][arow] = a4.y;
        As[acol + 2][arow] = a4.z;
        As[acol + 3][arow] = a4.w;
        float4 b4 = *reinterpret_cast<const float4*>(Wblk + (size_t)(k0 + brow) * N + bcol);
        *reinterpret_cast<float4*>(&Bs[brow][bcol]) = b4;
        __syncthreads();

        #pragma unroll
        for (int kk = 0; kk < GBK; kk++) {
            float ra[8], rb[8];
            *reinterpret_cast<float4*>(&ra[0]) = *reinterpret_cast<const float4*>(&As[kk][ty * 8]);
            *reinterpret_cast<float4*>(&ra[4]) = *reinterpret_cast<const float4*>(&As[kk][ty * 8 + 4]);
            *reinterpret_cast<float4*>(&rb[0]) = *reinterpret_cast<const float4*>(&Bs[kk][tx * 4]);
            *reinterpret_cast<float4*>(&rb[4]) = *reinterpret_cast<const float4*>(&Bs[kk][64 + tx * 4]);
            #pragma unroll
            for (int i = 0; i < 8; i++)
                #pragma unroll
                for (int j = 0; j < 8; j++)
                    acc[i][j] += ra[i] * rb[j];
        }
        __syncthreads();
    }

    const int row0 = by * GBM + ty * 8;
    const int colA = bx * GBN + tx * 4;
    const int colB = colA + 64;
    float4 biasA = *reinterpret_cast<const float4*>(bias + colA);
    float4 biasB = *reinterpret_cast<const float4*>(bias + colB);
    #pragma unroll
    for (int i = 0; i < 8; i++) {
        float4 oa, ob;
        oa.x = acc[i][0] + biasA.x;  oa.y = acc[i][1] + biasA.y;
        oa.z = acc[i][2] + biasA.z;  oa.w = acc[i][3] + biasA.w;
        ob.x = acc[i][4] + biasB.x;  ob.y = acc[i][5] + biasB.y;
        ob.z = acc[i][6] + biasB.z;  ob.w = acc[i][7] + biasB.w;
        *reinterpret_cast<float4*>(C + (size_t)(row0 + i) * N + colA) = oa;
        *reinterpret_cast<float4*>(C + (size_t)(row0 + i) * N + colB) = ob;
    }
}

// ============ RoPE: halves pairing, NEGATIVE rotation (hypothesis) =========
// pairs (i, i+64), angle = s * 10000^(-i/64), rotation by -theta:
//   out1 =  t1*cos + t2*sin
//   out2 = -t1*sin + t2*cos
__global__ __launch_bounds__(64) void rope_neg_kernel(
    float* __restrict__ Q, float* __restrict__ K)
{
    const int row = blockIdx.x;        // 0..4095
    const int h   = blockIdx.y;        // 0..15
    const int i   = threadIdx.x;       // 0..63
    const int s   = row & (SEQL - 1);

    const float inv = exp2f(-0.2076205059304601f * (float)i);  // log2(1e4)/64
    float c, sn;
    sincosf((float)s * inv, &c, &sn);

    const size_t off = (size_t)row * DM + (size_t)h * HDIM + i;
    float q1 = Q[off], q2 = Q[off + 64];
    Q[off]      =  q1 * c + q2 * sn;
    Q[off + 64] = -q1 * sn + q2 * c;
    float k1 = K[off], k2 = K[off + 64];
    K[off]      =  k1 * c + k2 * sn;
    K[off + 64] = -k1 * sn + k2 * c;
}

// ======================= Sliding-window attention ==========================
// One WARP per query row; 16 warps/CTA; 32-key tiles via static smem.
#define AQ  16
#define AKT 32

__global__ __launch_bounds__(512) void swattn_v3_kernel(
    const float* __restrict__ Q, const float* __restrict__ K,
    const float* __restrict__ V, const float* __restrict__ kw,
    float* __restrict__ O)
{
    __shared__ float sKt[AKT * HDIM];
    __shared__ float sVt[AKT * HDIM];

    const int tid  = threadIdx.x;
    const int lane = tid & 31;
    const int w    = tid >> 5;
    const int bh   = blockIdx.y;
    const int b    = bh >> 4;
    const int h    = bh & 15;
    const int i0   = blockIdx.x * AQ;
    const int i    = i0 + w;
    const float scale = kw[h] * 0.08838834764831845f;   // kw / sqrt(128)

    float4 q4 = *reinterpret_cast<const float4*>(
        Q + ((size_t)(b * SEQL + i)) * DM + (size_t)h * HDIM + 4 * lane);

    float  m    = -1e30f;
    float  lsum = 0.f;
    float4 acc  = make_float4(0.f, 0.f, 0.f, 0.f);

    int jt0 = i0 - WINDOW; if (jt0 < 0) jt0 = 0;
    jt0 &= ~(AKT - 1);
    const int jtend = (i0 + AQ - 1) & ~(AKT - 1);

    for (int jt = jt0; jt <= jtend; jt += AKT) {
        __syncthreads();
        {
            const float* Kg = K + ((size_t)(b * SEQL + jt)) * DM + (size_t)h * HDIM;
            const float* Vg = V + ((size_t)(b * SEQL + jt)) * DM + (size_t)h * HDIM;
            for (int idx = tid; idx < AKT * (HDIM / 4); idx += 512) {
                int r = idx >> 5, c = idx & 31;
                reinterpret_cast<float4*>(sKt)[idx] =
                    *reinterpret_cast<const float4*>(Kg + (size_t)r * DM + 4 * c);
                reinterpret_cast<float4*>(sVt)[idx] =
                    *reinterpret_cast<const float4*>(Vg + (size_t)r * DM + 4 * c);
            }
        }
        __syncthreads();

        float myscore = -1e30f;
        #pragma unroll
        for (int jj = 0; jj < AKT; jj++) {
            float4 k4 = reinterpret_cast<const float4*>(sKt)[jj * 32 + lane];
            float part = q4.x * k4.x + q4.y * k4.y + q4.z * k4.z + q4.w * k4.w;
            #pragma unroll
            for (int off = 16; off; off >>= 1)
                part += __shfl_xor_sync(0xffffffffu, part, off);
            int jg = jt + jj;
            float sc = (jg <= i && jg >= i - WINDOW) ? part * scale : -1e30f;
            if (lane == jj) myscore = sc;
        }

        float tm = myscore;
        #pragma unroll
        for (int off = 16; off; off >>= 1)
            tm = fmaxf(tm, __shfl_xor_sync(0xffffffffu, tm, off));

        float mnew  = fmaxf(m, tm);
        float alpha = expf(m - mnew);
        lsum *= alpha;
        acc.x *= alpha; acc.y *= alpha; acc.z *= alpha; acc.w *= alpha;

        #pragma unroll
        for (int jj = 0; jj < AKT; jj++) {
            float sc = __shfl_sync(0xffffffffu, myscore, jj);
            float p  = expf(sc - mnew);
            lsum += p;
            float4 v4 = reinterpret_cast<const float4*>(sVt)[jj * 32 + lane];
            acc.x += p * v4.x; acc.y += p * v4.y;
            acc.z += p * v4.z; acc.w += p * v4.w;
        }
        m = mnew;
    }

    const float inv = 1.0f / lsum;
    float4 o = make_float4(acc.x * inv, acc.y * inv, acc.z * inv, acc.w * inv);
    *reinterpret_cast<float4*>(
        O + ((size_t)(b * SEQL + i)) * DM + (size_t)h * HDIM + 4 * lane) = o;
}

// =============================== launch ====================================
extern "C" void kernel_launch(void* const* d_in, const int* in_sizes, int n_in,
                              void* d_out, int out_size)
{
    // size-based binding, appearance order (proved == dict order)
    const float* x = 0; const float* Ws[4] = {0,0,0,0};
    const float* bs[4] = {0,0,0,0}; const float* kww = 0;
    int nw = 0, nb = 0;
    for (int idx = 0; idx < n_in; idx++) {
        int sz = in_sizes[idx];
        const float* p = (const float*)d_in[idx];
        if      (sz == ROWS * HIDDEN) { if (!x) x = p; }
        else if (sz == HIDDEN * DM)   { if (nw < 4) Ws[nw++] = p; }
        else if (sz == DM)            { if (nb < 4) bs[nb++] = p; }
        else if (sz == NHEADS)        { if (!kww) kww = p; }
    }
    const float* W_Q = Ws[0]; const float* b_Q = bs[0];
    const float* W_K = Ws[1]; const float* b_K = bs[1];
    const float* W_V = Ws[2]; const float* b_V = bs[2];
    const float* W_O = Ws[3]; const float* b_O = bs[3];
    float* out = (float*)d_out;

    float *qp, *kp, *vp, *ap;
    cudaGetSymbolAddress((void**)&qp, s_Q);
    cudaGetSymbolAddress((void**)&kp, s_K);
    cudaGetSymbolAddress((void**)&vp, s_V);
    cudaGetSymbolAddress((void**)&ap, s_att);

    dim3 ggrid(DM / GBN, ROWS / GBM);   // (16, 32)
    sgemm_bias_kernel<<<ggrid, 256>>>(x, W_Q, b_Q, qp, ROWS, DM, HIDDEN);
    sgemm_bias_kernel<<<ggrid, 256>>>(x, W_K, b_K, kp, ROWS, DM, HIDDEN);
    sgemm_bias_kernel<<<ggrid, 256>>>(x, W_V, b_V, vp, ROWS, DM, HIDDEN);

    dim3 rgrid(ROWS, NHEADS);           // (4096, 16)
    rope_neg_kernel<<<rgrid, 64>>>(qp, kp);     // NEGATIVE rotation hypothesis

    dim3 agrid(SEQL / AQ, BATCHN * NHEADS);     // (128, 32)
    swattn_v3_kernel<<<agrid, 512>>>(qp, kp, vp, kww, ap);

    dim3 ogrid(HIDDEN / GBN, ROWS / GBM);
    sgemm_bias_kernel<<<ogrid, 256>>>(ap, W_O, b_O, out, ROWS, HIDDEN, DM);
}

// round 9
// speedup vs baseline: 1.7795x; 1.7795x over previous
#include <cuda_runtime.h>
#include <cuda_bf16.h>
#include <cstdint>
#include <math.h>

// Problem constants
#define HIDDEN 2048
#define NHEADS 16
#define HDIM   128
#define SEQL   2048
#define BATCHN 2
#define WINDOW 256
#define ROWS   (BATCHN * SEQL)   // 4096
#define DM     (NHEADS * HDIM)   // 2048
#define KDIM   2048              // all GEMMs are 4096 x 2048 x 2048

// -------------------- scratch (no allocations allowed) --------------------
__device__ float s_Q[ROWS * DM];
__device__ float s_K[ROWS * DM];
__device__ float s_V[ROWS * DM];
__device__ float s_att[ROWS * DM];
__device__ __nv_bfloat16 g_xhi[ROWS * HIDDEN];
__device__ __nv_bfloat16 g_xlo[ROWS * HIDDEN];
__device__ __nv_bfloat16 g_Whi[4 * KDIM * KDIM];   // [w][K][N] (no transpose)
__device__ __nv_bfloat16 g_Wlo[4 * KDIM * KDIM];
__device__ __nv_bfloat16 g_ahi[ROWS * DM];
__device__ __nv_bfloat16 g_alo[ROWS * DM];

// ======================= warp-MMA helpers (base-target PTX) ================
__device__ __forceinline__ uint32_t smem_u32(const void* p) {
    uint32_t a;
    asm("{ .reg .u64 t; cvta.to.shared.u64 t, %1; cvt.u32.u64 %0, t; }"
        : "=r"(a) : "l"(p));
    return a;
}
__device__ __forceinline__ void ldsm_x4(uint32_t& r0, uint32_t& r1,
                                        uint32_t& r2, uint32_t& r3, uint32_t a) {
    asm volatile("ldmatrix.sync.aligned.m8n8.x4.shared.b16 {%0,%1,%2,%3}, [%4];"
                 : "=r"(r0), "=r"(r1), "=r"(r2), "=r"(r3) : "r"(a));
}
__device__ __forceinline__ void ldsm_x2t(uint32_t& r0, uint32_t& r1, uint32_t a) {
    asm volatile("ldmatrix.sync.aligned.m8n8.x2.trans.shared.b16 {%0,%1}, [%2];"
                 : "=r"(r0), "=r"(r1) : "r"(a));
}
__device__ __forceinline__ void mma16816(float* d, const uint32_t* a,
                                         const uint32_t* b) {
    asm volatile(
        "mma.sync.aligned.m16n8k16.row.col.f32.bf16.bf16.f32 "
        "{%0,%1,%2,%3}, {%4,%5,%6,%7}, {%8,%9}, {%0,%1,%2,%3};"
        : "+f"(d[0]), "+f"(d[1]), "+f"(d[2]), "+f"(d[3])
        : "r"(a[0]), "r"(a[1]), "r"(a[2]), "r"(a[3]), "r"(b[0]), "r"(b[1]));
}
__device__ __forceinline__ void cpasync16(uint32_t dst, const void* src) {
    asm volatile("cp.async.cg.shared.global [%0], [%1], 16;"
                 :: "r"(dst), "l"(src));
}
#define CP_COMMIT() asm volatile("cp.async.commit_group;" ::: "memory")
#define CP_WAIT0()  asm volatile("cp.async.wait_group 0;" ::: "memory")

// ==================== conversion (split fp32 -> bf16 hi/lo) ================
__global__ void split_kernel(const float* __restrict__ src,
                             __nv_bfloat16* __restrict__ hi,
                             __nv_bfloat16* __restrict__ lo)
{
    size_t i = (size_t)blockIdx.x * blockDim.x + threadIdx.x;
    float v = src[i];
    __nv_bfloat16 h = __float2bfloat16(v);
    hi[i] = h;
    lo[i] = __float2bfloat16(v - __bfloat162float(h));
}

// ============ split-bf16 tensor-core GEMM: C = A@W + bias ==================
// CTA 128x128, K-chunk 32, 8 warps (2x4), warp tile 64x32.
// A [M,K] row-major bf16 hi/lo; W [K,N] row-major bf16 hi/lo.
// smem strides (bf16): A: 40 (rows of 32 + pad 8), B: 136 (rows of 128 + pad 8)
#define LDA 40
#define LDB 136
#define SZ_A (128 * LDA * 2)          // 10240 B
#define SZ_B (32 * LDB * 2)           // 8704 B
#define OFF_AHI 0
#define OFF_ALO SZ_A
#define OFF_BHI (2 * SZ_A)
#define OFF_BLO (2 * SZ_A + SZ_B)
#define BUFSZ   (2 * SZ_A + 2 * SZ_B) // 37888 B
#define GSMEM   (2 * BUFSZ)           // 75776 B

__global__ __launch_bounds__(256) void gemm_mma_kernel(
    const __nv_bfloat16* __restrict__ Ahi, const __nv_bfloat16* __restrict__ Alo,
    const __nv_bfloat16* __restrict__ Bhi, const __nv_bfloat16* __restrict__ Blo,
    const float* __restrict__ bias, float* __restrict__ C)
{
    extern __shared__ __align__(16) char sm[];
    const uint32_t smb = smem_u32(sm);
    const int tid  = threadIdx.x;
    const int lane = tid & 31;
    const int wid  = tid >> 5;
    const int wm   = (wid >> 2) * 64;   // warp row offset in CTA tile
    const int wn   = (wid & 3) * 32;    // warp col offset
    const int m0   = blockIdx.y * 128;
    const int n0   = blockIdx.x * 128;

    // per-thread cp.async source/dest mapping
    const int am  = tid >> 2;            // A row 0..63 (+64 on second pass)
    const int ak  = (tid & 3) << 3;      // A col 0/8/16/24
    const int bk  = tid >> 4;            // B row 0..15 (+16)
    const int bn  = (tid & 15) << 3;     // B col 0..120

    auto load_tile = [&](int it, int buf) {
        const int k0 = it * 32;
        const uint32_t base = smb + buf * BUFSZ;
        #pragma unroll
        for (int j = 0; j < 2; j++) {
            int m = am + j * 64;
            uint32_t da = (uint32_t)(m * LDA + ak) * 2;
            cpasync16(base + OFF_AHI + da, Ahi + (size_t)(m0 + m) * KDIM + k0 + ak);
            cpasync16(base + OFF_ALO + da, Alo + (size_t)(m0 + m) * KDIM + k0 + ak);
            int kb = bk + j * 16;
            uint32_t db = (uint32_t)(kb * LDB + bn) * 2;
            cpasync16(base + OFF_BHI + db, Bhi + (size_t)(k0 + kb) * KDIM + n0 + bn);
            cpasync16(base + OFF_BLO + db, Blo + (size_t)(k0 + kb) * KDIM + n0 + bn);
        }
        CP_COMMIT();
    };

    float acc[4][4][4];
    #pragma unroll
    for (int mi = 0; mi < 4; mi++)
        #pragma unroll
        for (int ni = 0; ni < 4; ni++)
            #pragma unroll
            for (int r = 0; r < 4; r++) acc[mi][ni][r] = 0.f;

    load_tile(0, 0);

    const int NIT = KDIM / 32;   // 64
    for (int it = 0; it < NIT; it++) {
        const int buf = it & 1;
        CP_WAIT0();
        __syncthreads();
        if (it + 1 < NIT) load_tile(it + 1, buf ^ 1);

        const uint32_t base = smb + buf * BUFSZ;
        #pragma unroll
        for (int ks = 0; ks < 32; ks += 16) {
            uint32_t ah[4][4], al[4][4], bh[4][2], bl[4][2];
            #pragma unroll
            for (int mi = 0; mi < 4; mi++) {
                uint32_t adr = base +
                    (uint32_t)((wm + mi * 16 + (lane & 15)) * LDA +
                               ks + ((lane >> 4) << 3)) * 2;
                ldsm_x4(ah[mi][0], ah[mi][1], ah[mi][2], ah[mi][3], adr + OFF_AHI);
                ldsm_x4(al[mi][0], al[mi][1], al[mi][2], al[mi][3], adr + OFF_ALO);
            }
            #pragma unroll
            for (int ni = 0; ni < 4; ni++) {
                uint32_t adr = base +
                    (uint32_t)((ks + (lane & 15)) * LDB + wn + ni * 8) * 2;
                ldsm_x2t(bh[ni][0], bh[ni][1], adr + OFF_BHI);
                ldsm_x2t(bl[ni][0], bl[ni][1], adr + OFF_BLO);
            }
            #pragma unroll
            for (int mi = 0; mi < 4; mi++)
                #pragma unroll
                for (int ni = 0; ni < 4; ni++) {
                    mma16816(acc[mi][ni], ah[mi], bh[ni]);
                    mma16816(acc[mi][ni], ah[mi], bl[ni]);
                    mma16816(acc[mi][ni], al[mi], bh[ni]);
                }
        }
        __syncthreads();
    }

    // epilogue: bias + store (c layout: d0,d1 -> (r, c..c+1); d2,d3 -> (r+8, ..))
    const int r  = lane >> 2;
    const int c  = (lane & 3) << 1;
    #pragma unroll
    for (int mi = 0; mi < 4; mi++) {
        const int m1 = m0 + wm + mi * 16 + r;
        #pragma unroll
        for (int ni = 0; ni < 4; ni++) {
            const int n = n0 + wn + ni * 8 + c;
            float2 bb = *reinterpret_cast<const float2*>(bias + n);
            float2 o0 = { acc[mi][ni][0] + bb.x, acc[mi][ni][1] + bb.y };
            float2 o1 = { acc[mi][ni][2] + bb.x, acc[mi][ni][3] + bb.y };
            *reinterpret_cast<float2*>(C + (size_t)m1 * KDIM + n)       = o0;
            *reinterpret_cast<float2*>(C + (size_t)(m1 + 8) * KDIM + n) = o1;
        }
    }
}

// ============ RoPE: halves pairing, NEGATIVE rotation (verified) ===========
__global__ __launch_bounds__(64) void rope_neg_kernel(
    float* __restrict__ Q, float* __restrict__ K)
{
    const int row = blockIdx.x;
    const int h   = blockIdx.y;
    const int i   = threadIdx.x;
    const int s   = row & (SEQL - 1);

    const float inv = exp2f(-0.2076205059304601f * (float)i);
    float c, sn;
    sincosf((float)s * inv, &c, &sn);

    const size_t off = (size_t)row * DM + (size_t)h * HDIM + i;
    float q1 = Q[off], q2 = Q[off + 64];
    Q[off]      =  q1 * c + q2 * sn;
    Q[off + 64] = -q1 * sn + q2 * c;
    float k1 = K[off], k2 = K[off + 64];
    K[off]      =  k1 * c + k2 * sn;
    K[off + 64] = -k1 * sn + k2 * c;
}

// ======================= Sliding-window attention (verified) ===============
#define AQ  16
#define AKT 32

__global__ __launch_bounds__(512) void swattn_v3_kernel(
    const float* __restrict__ Q, const float* __restrict__ K,
    const float* __restrict__ V, const float* __restrict__ kw,
    float* __restrict__ O)
{
    __shared__ float sKt[AKT * HDIM];
    __shared__ float sVt[AKT * HDIM];

    const int tid  = threadIdx.x;
    const int lane = tid & 31;
    const int w    = tid >> 5;
    const int bh   = blockIdx.y;
    const int b    = bh >> 4;
    const int h    = bh & 15;
    const int i0   = blockIdx.x * AQ;
    const int i    = i0 + w;
    const float scale = kw[h] * 0.08838834764831845f;

    float4 q4 = *reinterpret_cast<const float4*>(
        Q + ((size_t)(b * SEQL + i)) * DM + (size_t)h * HDIM + 4 * lane);

    float  m    = -1e30f;
    float  lsum = 0.f;
    float4 acc  = make_float4(0.f, 0.f, 0.f, 0.f);

    int jt0 = i0 - WINDOW; if (jt0 < 0) jt0 = 0;
    jt0 &= ~(AKT - 1);
    const int jtend = (i0 + AQ - 1) & ~(AKT - 1);

    for (int jt = jt0; jt <= jtend; jt += AKT) {
        __syncthreads();
        {
            const float* Kg = K + ((size_t)(b * SEQL + jt)) * DM + (size_t)h * HDIM;
            const float* Vg = V + ((size_t)(b * SEQL + jt)) * DM + (size_t)h * HDIM;
            for (int idx = tid; idx < AKT * (HDIM / 4); idx += 512) {
                int r = idx >> 5, c = idx & 31;
                reinterpret_cast<float4*>(sKt)[idx] =
                    *reinterpret_cast<const float4*>(Kg + (size_t)r * DM + 4 * c);
                reinterpret_cast<float4*>(sVt)[idx] =
                    *reinterpret_cast<const float4*>(Vg + (size_t)r * DM + 4 * c);
            }
        }
        __syncthreads();

        float myscore = -1e30f;
        #pragma unroll
        for (int jj = 0; jj < AKT; jj++) {
            float4 k4 = reinterpret_cast<const float4*>(sKt)[jj * 32 + lane];
            float part = q4.x * k4.x + q4.y * k4.y + q4.z * k4.z + q4.w * k4.w;
            #pragma unroll
            for (int off = 16; off; off >>= 1)
                part += __shfl_xor_sync(0xffffffffu, part, off);
            int jg = jt + jj;
            float sc = (jg <= i && jg >= i - WINDOW) ? part * scale : -1e30f;
            if (lane == jj) myscore = sc;
        }

        float tm = myscore;
        #pragma unroll
        for (int off = 16; off; off >>= 1)
            tm = fmaxf(tm, __shfl_xor_sync(0xffffffffu, tm, off));

        float mnew  = fmaxf(m, tm);
        float alpha = expf(m - mnew);
        lsum *= alpha;
        acc.x *= alpha; acc.y *= alpha; acc.z *= alpha; acc.w *= alpha;

        #pragma unroll
        for (int jj = 0; jj < AKT; jj++) {
            float sc = __shfl_sync(0xffffffffu, myscore, jj);
            float p  = expf(sc - mnew);
            lsum += p;
            float4 v4 = reinterpret_cast<const float4*>(sVt)[jj * 32 + lane];
            acc.x += p * v4.x; acc.y += p * v4.y;
            acc.z += p * v4.z; acc.w += p * v4.w;
        }
        m = mnew;
    }

    const float inv = 1.0f / lsum;
    float4 o = make_float4(acc.x * inv, acc.y * inv, acc.z * inv, acc.w * inv);
    *reinterpret_cast<float4*>(
        O + ((size_t)(b * SEQL + i)) * DM + (size_t)h * HDIM + 4 * lane) = o;
}

// =============================== launch ====================================
extern "C" void kernel_launch(void* const* d_in, const int* in_sizes, int n_in,
                              void* d_out, int out_size)
{
    const float* x = 0; const float* Ws[4] = {0,0,0,0};
    const float* bs[4] = {0,0,0,0}; const float* kww = 0;
    int nw = 0, nb = 0;
    for (int idx = 0; idx < n_in; idx++) {
        int sz = in_sizes[idx];
        const float* p = (const float*)d_in[idx];
        if      (sz == ROWS * HIDDEN) { if (!x) x = p; }
        else if (sz == HIDDEN * DM)   { if (nw < 4) Ws[nw++] = p; }
        else if (sz == DM)            { if (nb < 4) bs[nb++] = p; }
        else if (sz == NHEADS)        { if (!kww) kww = p; }
    }
    float* out = (float*)d_out;

    float *qp, *kp, *vp, *ap;
    __nv_bfloat16 *xhi, *xlo, *whi, *wlo, *ahi, *alo;
    cudaGetSymbolAddress((void**)&qp,  s_Q);
    cudaGetSymbolAddress((void**)&kp,  s_K);
    cudaGetSymbolAddress((void**)&vp,  s_V);
    cudaGetSymbolAddress((void**)&ap,  s_att);
    cudaGetSymbolAddress((void**)&xhi, g_xhi);
    cudaGetSymbolAddress((void**)&xlo, g_xlo);
    cudaGetSymbolAddress((void**)&whi, g_Whi);
    cudaGetSymbolAddress((void**)&wlo, g_Wlo);
    cudaGetSymbolAddress((void**)&ahi, g_ahi);
    cudaGetSymbolAddress((void**)&alo, g_alo);

    cudaFuncSetAttribute(gemm_mma_kernel,
                         cudaFuncAttributeMaxDynamicSharedMemorySize, GSMEM);

    // conversions (pure elementwise — no transpose needed for mma.sync path)
    split_kernel<<<(ROWS * HIDDEN) / 256, 256>>>(x, xhi, xlo);
    for (int wdx = 0; wdx < 4; wdx++)
        split_kernel<<<(KDIM * KDIM) / 256, 256>>>(Ws[wdx],
            whi + (size_t)wdx * KDIM * KDIM, wlo + (size_t)wdx * KDIM * KDIM);

    // QKV projections
    dim3 ggrid(KDIM / 128, ROWS / 128);   // (16, 32)
    gemm_mma_kernel<<<ggrid, 256, GSMEM>>>(xhi, xlo,
        whi + 0 * (size_t)KDIM * KDIM, wlo + 0 * (size_t)KDIM * KDIM, bs[0], qp);
    gemm_mma_kernel<<<ggrid, 256, GSMEM>>>(xhi, xlo,
        whi + 1 * (size_t)KDIM * KDIM, wlo + 1 * (size_t)KDIM * KDIM, bs[1], kp);
    gemm_mma_kernel<<<ggrid, 256, GSMEM>>>(xhi, xlo,
        whi + 2 * (size_t)KDIM * KDIM, wlo + 2 * (size_t)KDIM * KDIM, bs[2], vp);

    dim3 rgrid(ROWS, NHEADS);
    rope_neg_kernel<<<rgrid, 64>>>(qp, kp);

    dim3 agrid(SEQL / AQ, BATCHN * NHEADS);
    swattn_v3_kernel<<<agrid, 512>>>(qp, kp, vp, kww, ap);

    // O projection
    split_kernel<<<(ROWS * DM) / 256, 256>>>(ap, ahi, alo);
    gemm_mma_kernel<<<ggrid, 256, GSMEM>>>(ahi, alo,
        whi + 3 * (size_t)KDIM * KDIM, wlo + 3 * (size_t)KDIM * KDIM, bs[3], out);
}

// round 10
// speedup vs baseline: 1.9572x; 1.0999x over previous
#include <cuda_runtime.h>
#include <cuda_fp16.h>
#include <cstdint>
#include <math.h>

// Problem constants
#define HIDDEN 2048
#define NHEADS 16
#define HDIM   128
#define SEQL   2048
#define BATCHN 2
#define WINDOW 256
#define ROWS   (BATCHN * SEQL)   // 4096
#define DM     (NHEADS * HDIM)   // 2048
#define KDIM   2048

// -------------------- scratch (no allocations allowed) --------------------
__device__ float  s_Q[ROWS * DM];
__device__ float  s_K[ROWS * DM];
__device__ float  s_V[ROWS * DM];
__device__ float  s_att[ROWS * DM];
__device__ __half g_xh[ROWS * HIDDEN];          // x as fp16 (unsplit)
__device__ __half g_Whi[4 * KDIM * KDIM];       // W hi, [w][K][N]
__device__ __half g_Wlo[4 * KDIM * KDIM];       // W lo
__device__ __half g_ah[ROWS * DM];              // attention out as fp16

// ======================= warp-MMA helpers (base-target PTX) ================
__device__ __forceinline__ uint32_t smem_u32(const void* p) {
    uint32_t a;
    asm("{ .reg .u64 t; cvta.to.shared.u64 t, %1; cvt.u32.u64 %0, t; }"
        : "=r"(a) : "l"(p));
    return a;
}
__device__ __forceinline__ void ldsm_x4(uint32_t& r0, uint32_t& r1,
                                        uint32_t& r2, uint32_t& r3, uint32_t a) {
    asm volatile("ldmatrix.sync.aligned.m8n8.x4.shared.b16 {%0,%1,%2,%3}, [%4];"
                 : "=r"(r0), "=r"(r1), "=r"(r2), "=r"(r3) : "r"(a));
}
__device__ __forceinline__ void ldsm_x2t(uint32_t& r0, uint32_t& r1, uint32_t a) {
    asm volatile("ldmatrix.sync.aligned.m8n8.x2.trans.shared.b16 {%0,%1}, [%2];"
                 : "=r"(r0), "=r"(r1) : "r"(a));
}
__device__ __forceinline__ void mma16816h(float* d, const uint32_t* a,
                                          const uint32_t* b) {
    asm volatile(
        "mma.sync.aligned.m16n8k16.row.col.f32.f16.f16.f32 "
        "{%0,%1,%2,%3}, {%4,%5,%6,%7}, {%8,%9}, {%0,%1,%2,%3};"
        : "+f"(d[0]), "+f"(d[1]), "+f"(d[2]), "+f"(d[3])
        : "r"(a[0]), "r"(a[1]), "r"(a[2]), "r"(a[3]), "r"(b[0]), "r"(b[1]));
}
__device__ __forceinline__ void cpasync16(uint32_t dst, const void* src) {
    asm volatile("cp.async.cg.shared.global [%0], [%1], 16;"
                 :: "r"(dst), "l"(src));
}
#define CP_COMMIT() asm volatile("cp.async.commit_group;" ::: "memory")
#define CP_WAIT0()  asm volatile("cp.async.wait_group 0;" ::: "memory")

// ==================== conversion kernels ===================================
__global__ void cvt_half_kernel(const float* __restrict__ src,
                                __half* __restrict__ dst)
{
    size_t i = (size_t)blockIdx.x * blockDim.x + threadIdx.x;
    dst[i] = __float2half(src[i]);
}

struct WPtrs { const float* p[4]; };
__global__ void splitW_kernel(WPtrs w, __half* __restrict__ hi,
                              __half* __restrict__ lo)
{
    size_t gid = (size_t)blockIdx.x * blockDim.x + threadIdx.x;
    float v = w.p[gid >> 22][gid & 0x3FFFFFu];   // KDIM*KDIM = 2^22
    __half h = __float2half(v);
    hi[gid] = h;
    lo[gid] = __float2half(v - __half2float(h));
}

// ============ fp16 2-term tensor-core GEMM: C = A@W + bias =================
// A [M,K] fp16 (unsplit); W [K,N] fp16 hi/lo. C = A*Whi + A*Wlo (fp32 acc).
// CTA 128x128, K-chunk 32, 8 warps (2x4), warp tile 64x32.
#define LDA 40
#define LDB 136
#define SZ_A (128 * LDA * 2)          // 10240 B
#define SZ_B (32 * LDB * 2)           // 8704 B
#define OFF_A   0
#define OFF_BHI SZ_A
#define OFF_BLO (SZ_A + SZ_B)
#define BUFSZ   (SZ_A + 2 * SZ_B)     // 27648 B
#define GSMEM   (2 * BUFSZ)           // 55296 B

__global__ __launch_bounds__(256) void gemm_mma_kernel(
    const __half* __restrict__ A,
    const __half* __restrict__ Bhi, const __half* __restrict__ Blo,
    const float* __restrict__ bias, float* __restrict__ C)
{
    extern __shared__ __align__(16) char sm[];
    const uint32_t smb = smem_u32(sm);
    const int tid  = threadIdx.x;
    const int lane = tid & 31;
    const int wid  = tid >> 5;
    const int wm   = (wid >> 2) * 64;
    const int wn   = (wid & 3) * 32;
    const int m0   = blockIdx.y * 128;
    const int n0   = blockIdx.x * 128;

    const int am  = tid >> 2;            // A row 0..63 (+64)
    const int ak  = (tid & 3) << 3;      // A col 0/8/16/24
    const int bk  = tid >> 4;            // B row 0..15 (+16)
    const int bn  = (tid & 15) << 3;     // B col 0..120

    auto load_tile = [&](int it, int buf) {
        const int k0 = it * 32;
        const uint32_t base = smb + buf * BUFSZ;
        #pragma unroll
        for (int j = 0; j < 2; j++) {
            int m = am + j * 64;
            cpasync16(base + OFF_A + (uint32_t)(m * LDA + ak) * 2,
                      A + (size_t)(m0 + m) * KDIM + k0 + ak);
            int kb = bk + j * 16;
            uint32_t db = (uint32_t)(kb * LDB + bn) * 2;
            cpasync16(base + OFF_BHI + db, Bhi + (size_t)(k0 + kb) * KDIM + n0 + bn);
            cpasync16(base + OFF_BLO + db, Blo + (size_t)(k0 + kb) * KDIM + n0 + bn);
        }
        CP_COMMIT();
    };

    float acc[4][4][4];
    #pragma unroll
    for (int mi = 0; mi < 4; mi++)
        #pragma unroll
        for (int ni = 0; ni < 4; ni++)
            #pragma unroll
            for (int r = 0; r < 4; r++) acc[mi][ni][r] = 0.f;

    load_tile(0, 0);

    const int NIT = KDIM / 32;
    for (int it = 0; it < NIT; it++) {
        const int buf = it & 1;
        CP_WAIT0();
        __syncthreads();
        if (it + 1 < NIT) load_tile(it + 1, buf ^ 1);

        const uint32_t base = smb + buf * BUFSZ;
        #pragma unroll
        for (int ks = 0; ks < 32; ks += 16) {
            uint32_t ah[4][4], bh[4][2], bl[4][2];
            #pragma unroll
            for (int mi = 0; mi < 4; mi++) {
                uint32_t adr = base + OFF_A +
                    (uint32_t)((wm + mi * 16 + (lane & 15)) * LDA +
                               ks + ((lane >> 4) << 3)) * 2;
                ldsm_x4(ah[mi][0], ah[mi][1], ah[mi][2], ah[mi][3], adr);
            }
            #pragma unroll
            for (int ni = 0; ni < 4; ni++) {
                uint32_t adr = base +
                    (uint32_t)((ks + (lane & 15)) * LDB + wn + ni * 8) * 2;
                ldsm_x2t(bh[ni][0], bh[ni][1], adr + OFF_BHI);
                ldsm_x2t(bl[ni][0], bl[ni][1], adr + OFF_BLO);
            }
            #pragma unroll
            for (int mi = 0; mi < 4; mi++)
                #pragma unroll
                for (int ni = 0; ni < 4; ni++) {
                    mma16816h(acc[mi][ni], ah[mi], bh[ni]);
                    mma16816h(acc[mi][ni], ah[mi], bl[ni]);
                }
        }
        __syncthreads();
    }

    const int r = lane >> 2;
    const int c = (lane & 3) << 1;
    #pragma unroll
    for (int mi = 0; mi < 4; mi++) {
        const int m1 = m0 + wm + mi * 16 + r;
        #pragma unroll
        for (int ni = 0; ni < 4; ni++) {
            const int n = n0 + wn + ni * 8 + c;
            float2 bb = *reinterpret_cast<const float2*>(bias + n);
            float2 o0 = { acc[mi][ni][0] + bb.x, acc[mi][ni][1] + bb.y };
            float2 o1 = { acc[mi][ni][2] + bb.x, acc[mi][ni][3] + bb.y };
            *reinterpret_cast<float2*>(C + (size_t)m1 * KDIM + n)       = o0;
            *reinterpret_cast<float2*>(C + (size_t)(m1 + 8) * KDIM + n) = o1;
        }
    }
}

// ============== Sliding-window attention with fused RoPE ===================
// One WARP per query; 16 warps/CTA; 32-key tiles in static smem.
// RoPE (halves pairing, NEGATIVE rotation — verified): applied to the Q
// fragment via shfl (lane l <-> l^16 holds the d+-64 partner) and to each
// K tile in-smem after load. V untouched.
#define AQ  16
#define AKT 32
#define ROPE_L2 0.2076205059304601f   // log2(10000)/64

__global__ __launch_bounds__(512) void swattn_rope_kernel(
    const float* __restrict__ Q, const float* __restrict__ K,
    const float* __restrict__ V, const float* __restrict__ kw,
    float* __restrict__ O)
{
    __shared__ float sKt[AKT * HDIM];
    __shared__ float sVt[AKT * HDIM];

    const int tid  = threadIdx.x;
    const int lane = tid & 31;
    const int w    = tid >> 5;
    const int bh   = blockIdx.y;
    const int b    = bh >> 4;
    const int h    = bh & 15;
    const int i0   = blockIdx.x * AQ;
    const int i    = i0 + w;              // query pos in sequence
    const float scale = kw[h] * 0.08838834764831845f;

    // ---- load + rope Q fragment (lane l: dims 4l..4l+3) ----
    float4 q4 = *reinterpret_cast<const float4*>(
        Q + ((size_t)(b * SEQL + i)) * DM + (size_t)h * HDIM + 4 * lane);
    {
        float4 qp;
        qp.x = __shfl_xor_sync(0xffffffffu, q4.x, 16);
        qp.y = __shfl_xor_sync(0xffffffffu, q4.y, 16);
        qp.z = __shfl_xor_sync(0xffffffffu, q4.z, 16);
        qp.w = __shfl_xor_sync(0xffffffffu, q4.w, 16);
        float qa[4] = {q4.x, q4.y, q4.z, q4.w};
        float pa[4] = {qp.x, qp.y, qp.z, qp.w};
        const float sgn = (lane < 16) ? 1.f : -1.f;
        #pragma unroll
        for (int c = 0; c < 4; c++) {
            int fi = (4 * lane + c) & 63;
            float inv = exp2f(-ROPE_L2 * (float)fi);
            float cs, sn;
            sincosf((float)i * inv, &cs, &sn);
            qa[c] = qa[c] * cs + sgn * pa[c] * sn;
        }
        q4.x = qa[0]; q4.y = qa[1]; q4.z = qa[2]; q4.w = qa[3];
    }

    float  m    = -1e30f;
    float  lsum = 0.f;
    float4 acc  = make_float4(0.f, 0.f, 0.f, 0.f);

    int jt0 = i0 - WINDOW; if (jt0 < 0) jt0 = 0;
    jt0 &= ~(AKT - 1);
    const int jtend = (i0 + AQ - 1) & ~(AKT - 1);

    for (int jt = jt0; jt <= jtend; jt += AKT) {
        __syncthreads();
        {
            const float* Kg = K + ((size_t)(b * SEQL + jt)) * DM + (size_t)h * HDIM;
            const float* Vg = V + ((size_t)(b * SEQL + jt)) * DM + (size_t)h * HDIM;
            for (int idx = tid; idx < AKT * (HDIM / 4); idx += 512) {
                int r = idx >> 5, c = idx & 31;
                reinterpret_cast<float4*>(sKt)[idx] =
                    *reinterpret_cast<const float4*>(Kg + (size_t)r * DM + 4 * c);
                reinterpret_cast<float4*>(sVt)[idx] =
                    *reinterpret_cast<const float4*>(Vg + (size_t)r * DM + 4 * c);
            }
        }
        __syncthreads();

        // ---- rope K tile in smem: thread -> (key r, dim chunk c0..c0+3) ----
        {
            const int r  = tid >> 4;          // 0..31
            const int c0 = (tid & 15) * 4;    // 0..60
            float4 f1 = *reinterpret_cast<float4*>(&sKt[r * HDIM + c0]);
            float4 f2 = *reinterpret_cast<float4*>(&sKt[r * HDIM + c0 + 64]);
            const float sp = (float)(jt + r);
            float a1[4] = {f1.x, f1.y, f1.z, f1.w};
            float a2[4] = {f2.x, f2.y, f2.z, f2.w};
            #pragma unroll
            for (int c = 0; c < 4; c++) {
                float inv = exp2f(-ROPE_L2 * (float)(c0 + c));
                float cs, sn;
                sincosf(sp * inv, &cs, &sn);
                float t1 = a1[c], t2 = a2[c];
                a1[c] =  t1 * cs + t2 * sn;
                a2[c] = -t1 * sn + t2 * cs;
            }
            f1.x = a1[0]; f1.y = a1[1]; f1.z = a1[2]; f1.w = a1[3];
            f2.x = a2[0]; f2.y = a2[1]; f2.z = a2[2]; f2.w = a2[3];
            *reinterpret_cast<float4*>(&sKt[r * HDIM + c0])      = f1;
            *reinterpret_cast<float4*>(&sKt[r * HDIM + c0 + 64]) = f2;
        }
        __syncthreads();

        float myscore = -1e30f;
        #pragma unroll
        for (int jj = 0; jj < AKT; jj++) {
            float4 k4 = reinterpret_cast<const float4*>(sKt)[jj * 32 + lane];
            float part = q4.x * k4.x + q4.y * k4.y + q4.z * k4.z + q4.w * k4.w;
            #pragma unroll
            for (int off = 16; off; off >>= 1)
                part += __shfl_xor_sync(0xffffffffu, part, off);
            int jg = jt + jj;
            float sc = (jg <= i && jg >= i - WINDOW) ? part * scale : -1e30f;
            if (lane == jj) myscore = sc;
        }

        float tm = myscore;
        #pragma unroll
        for (int off = 16; off; off >>= 1)
            tm = fmaxf(tm, __shfl_xor_sync(0xffffffffu, tm, off));

        float mnew  = fmaxf(m, tm);
        float alpha = expf(m - mnew);
        lsum *= alpha;
        acc.x *= alpha; acc.y *= alpha; acc.z *= alpha; acc.w *= alpha;

        #pragma unroll
        for (int jj = 0; jj < AKT; jj++) {
            float sc = __shfl_sync(0xffffffffu, myscore, jj);
            float p  = expf(sc - mnew);
            lsum += p;
            float4 v4 = reinterpret_cast<const float4*>(sVt)[jj * 32 + lane];
            acc.x += p * v4.x; acc.y += p * v4.y;
            acc.z += p * v4.z; acc.w += p * v4.w;
        }
        m = mnew;
    }

    const float inv = 1.0f / lsum;
    float4 o = make_float4(acc.x * inv, acc.y * inv, acc.z * inv, acc.w * inv);
    *reinterpret_cast<float4*>(
        O + ((size_t)(b * SEQL + i)) * DM + (size_t)h * HDIM + 4 * lane) = o;
}

// =============================== launch ====================================
extern "C" void kernel_launch(void* const* d_in, const int* in_sizes, int n_in,
                              void* d_out, int out_size)
{
    const float* x = 0; const float* Ws[4] = {0,0,0,0};
    const float* bs[4] = {0,0,0,0}; const float* kww = 0;
    int nw = 0, nb = 0;
    for (int idx = 0; idx < n_in; idx++) {
        int sz = in_sizes[idx];
        const float* p = (const float*)d_in[idx];
        if      (sz == ROWS * HIDDEN) { if (!x) x = p; }
        else if (sz == HIDDEN * DM)   { if (nw < 4) Ws[nw++] = p; }
        else if (sz == DM)            { if (nb < 4) bs[nb++] = p; }
        else if (sz == NHEADS)        { if (!kww) kww = p; }
    }
    float* out = (float*)d_out;

    float *qp, *kp, *vp, *ap;
    __half *xh, *whi, *wlo, *ah;
    cudaGetSymbolAddress((void**)&qp,  s_Q);
    cudaGetSymbolAddress((void**)&kp,  s_K);
    cudaGetSymbolAddress((void**)&vp,  s_V);
    cudaGetSymbolAddress((void**)&ap,  s_att);
    cudaGetSymbolAddress((void**)&xh,  g_xh);
    cudaGetSymbolAddress((void**)&whi, g_Whi);
    cudaGetSymbolAddress((void**)&wlo, g_Wlo);
    cudaGetSymbolAddress((void**)&ah,  g_ah);

    cudaFuncSetAttribute(gemm_mma_kernel,
                         cudaFuncAttributeMaxDynamicSharedMemorySize, GSMEM);

    // (1) x -> fp16
    cvt_half_kernel<<<(ROWS * HIDDEN) / 256, 256>>>(x, xh);
    // (2) all four W -> fp16 hi/lo, one launch
    WPtrs wp; wp.p[0] = Ws[0]; wp.p[1] = Ws[1]; wp.p[2] = Ws[2]; wp.p[3] = Ws[3];
    splitW_kernel<<<(4 * KDIM * KDIM) / 256, 256>>>(wp, whi, wlo);

    // (3..5) QKV projections
    dim3 ggrid(KDIM / 128, ROWS / 128);
    gemm_mma_kernel<<<ggrid, 256, GSMEM>>>(xh,
        whi + 0 * (size_t)KDIM * KDIM, wlo + 0 * (size_t)KDIM * KDIM, bs[0], qp);
    gemm_mma_kernel<<<ggrid, 256, GSMEM>>>(xh,
        whi + 1 * (size_t)KDIM * KDIM, wlo + 1 * (size_t)KDIM * KDIM, bs[1], kp);
    gemm_mma_kernel<<<ggrid, 256, GSMEM>>>(xh,
        whi + 2 * (size_t)KDIM * KDIM, wlo + 2 * (size_t)KDIM * KDIM, bs[2], vp);

    // (6) attention with fused RoPE
    dim3 agrid(SEQL / AQ, BATCHN * NHEADS);
    swattn_rope_kernel<<<agrid, 512>>>(qp, kp, vp, kww, ap);

    // (7) attention out -> fp16, (8) O projection
    cvt_half_kernel<<<(ROWS * DM) / 256, 256>>>(ap, ah);
    gemm_mma_kernel<<<ggrid, 256, GSMEM>>>(ah,
        whi + 3 * (size_t)KDIM * KDIM, wlo + 3 * (size_t)KDIM * KDIM, bs[3], out);
}

// round 12
// speedup vs baseline: 3.7718x; 1.9272x over previous
#include <cuda_runtime.h>
#include <cuda_fp16.h>
#include <cstdint>
#include <string.h>
#include <math.h>

// Problem constants
#define HIDDEN 2048
#define NHEADS 16
#define HDIM   128
#define SEQL   2048
#define BATCHN 2
#define WINDOW 256
#define ROWS   (BATCHN * SEQL)   // 4096
#define DM     (NHEADS * HDIM)   // 2048
#define KDIM   2048

// -------------------- scratch (no allocations allowed) --------------------
__device__ float  s_Q[ROWS * DM];
__device__ float  s_K[ROWS * DM];
__device__ float  s_V[ROWS * DM];
__device__ __half g_xh[ROWS * HIDDEN];
__device__ __half g_Whi[4 * KDIM * KDIM];
__device__ __half g_Wlo[4 * KDIM * KDIM];
__device__ __half g_Qh[ROWS * DM];      // roped Q, fp16
__device__ __half g_Kh[ROWS * DM];      // roped K, fp16
__device__ __half g_Vh[ROWS * DM];      // V, fp16
__device__ __half g_ah[ROWS * DM];      // attention out, fp16

// ======================= PTX helpers =======================================
__device__ __forceinline__ uint32_t smem_u32(const void* p) {
    uint32_t a;
    asm("{ .reg .u64 t; cvta.to.shared.u64 t, %1; cvt.u32.u64 %0, t; }"
        : "=r"(a) : "l"(p));
    return a;
}
__device__ __forceinline__ uint32_t h2u(__half2 v) {
    uint32_t u;
    memcpy(&u, &v, 4);
    return u;
}
__device__ __forceinline__ void ldsm_x4(uint32_t& r0, uint32_t& r1,
                                        uint32_t& r2, uint32_t& r3, uint32_t a) {
    asm volatile("ldmatrix.sync.aligned.m8n8.x4.shared.b16 {%0,%1,%2,%3}, [%4];"
                 : "=r"(r0), "=r"(r1), "=r"(r2), "=r"(r3) : "r"(a));
}
__device__ __forceinline__ void ldsm_x4t(uint32_t& r0, uint32_t& r1,
                                         uint32_t& r2, uint32_t& r3, uint32_t a) {
    asm volatile("ldmatrix.sync.aligned.m8n8.x4.trans.shared.b16 {%0,%1,%2,%3}, [%4];"
                 : "=r"(r0), "=r"(r1), "=r"(r2), "=r"(r3) : "r"(a));
}
__device__ __forceinline__ void ldsm_x2(uint32_t& r0, uint32_t& r1, uint32_t a) {
    asm volatile("ldmatrix.sync.aligned.m8n8.x2.shared.b16 {%0,%1}, [%2];"
                 : "=r"(r0), "=r"(r1) : "r"(a));
}
__device__ __forceinline__ void ldsm_x2t(uint32_t& r0, uint32_t& r1, uint32_t a) {
    asm volatile("ldmatrix.sync.aligned.m8n8.x2.trans.shared.b16 {%0,%1}, [%2];"
                 : "=r"(r0), "=r"(r1) : "r"(a));
}
__device__ __forceinline__ void mma16816h(float* d, const uint32_t* a,
                                          const uint32_t* b) {
    asm volatile(
        "mma.sync.aligned.m16n8k16.row.col.f32.f16.f16.f32 "
        "{%0,%1,%2,%3}, {%4,%5,%6,%7}, {%8,%9}, {%0,%1,%2,%3};"
        : "+f"(d[0]), "+f"(d[1]), "+f"(d[2]), "+f"(d[3])
        : "r"(a[0]), "r"(a[1]), "r"(a[2]), "r"(a[3]), "r"(b[0]), "r"(b[1]));
}
__device__ __forceinline__ void cpasync16(uint32_t dst, const void* src) {
    asm volatile("cp.async.cg.shared.global [%0], [%1], 16;"
                 :: "r"(dst), "l"(src));
}
#define CP_COMMIT() asm volatile("cp.async.commit_group;" ::: "memory")
#define CP_WAIT0()  asm volatile("cp.async.wait_group 0;" ::: "memory")

// ================= prep: W -> fp16 hi/lo, x -> fp16 (one launch) ===========
struct WPtrs { const float* p[4]; };
#define WTOT (4u * KDIM * KDIM)   // 16777216
__global__ void prep_kernel(WPtrs w, const float* __restrict__ x,
                            __half* __restrict__ whi, __half* __restrict__ wlo,
                            __half* __restrict__ xh)
{
    size_t gid = (size_t)blockIdx.x * blockDim.x + threadIdx.x;
    if (gid < WTOT) {
        float v = w.p[gid >> 22][gid & 0x3FFFFFu];
        __half h = __float2half(v);
        whi[gid] = h;
        wlo[gid] = __float2half(v - __half2float(h));
    } else {
        size_t i = gid - WTOT;
        xh[i] = __float2half(x[i]);
    }
}

// ============ fp16 2-term tensor-core GEMM: C = A@W + bias (verified) ======
#define LDA 40
#define LDB 136
#define SZ_A (128 * LDA * 2)
#define SZ_B (32 * LDB * 2)
#define OFF_A   0
#define OFF_BHI SZ_A
#define OFF_BLO (SZ_A + SZ_B)
#define BUFSZ   (SZ_A + 2 * SZ_B)
#define GSMEM   (2 * BUFSZ)

__global__ __launch_bounds__(256) void gemm_mma_kernel(
    const __half* __restrict__ A,
    const __half* __restrict__ Bhi, const __half* __restrict__ Blo,
    const float* __restrict__ bias, float* __restrict__ C)
{
    extern __shared__ __align__(16) char sm[];
    const uint32_t smb = smem_u32(sm);
    const int tid  = threadIdx.x;
    const int lane = tid & 31;
    const int wid  = tid >> 5;
    const int wm   = (wid >> 2) * 64;
    const int wn   = (wid & 3) * 32;
    const int m0   = blockIdx.y * 128;
    const int n0   = blockIdx.x * 128;

    const int am  = tid >> 2;
    const int ak  = (tid & 3) << 3;
    const int bk  = tid >> 4;
    const int bn  = (tid & 15) << 3;

    auto load_tile = [&](int it, int buf) {
        const int k0 = it * 32;
        const uint32_t base = smb + buf * BUFSZ;
        #pragma unroll
        for (int j = 0; j < 2; j++) {
            int m = am + j * 64;
            cpasync16(base + OFF_A + (uint32_t)(m * LDA + ak) * 2,
                      A + (size_t)(m0 + m) * KDIM + k0 + ak);
            int kb = bk + j * 16;
            uint32_t db = (uint32_t)(kb * LDB + bn) * 2;
            cpasync16(base + OFF_BHI + db, Bhi + (size_t)(k0 + kb) * KDIM + n0 + bn);
            cpasync16(base + OFF_BLO + db, Blo + (size_t)(k0 + kb) * KDIM + n0 + bn);
        }
        CP_COMMIT();
    };

    float acc[4][4][4];
    #pragma unroll
    for (int mi = 0; mi < 4; mi++)
        #pragma unroll
        for (int ni = 0; ni < 4; ni++)
            #pragma unroll
            for (int r = 0; r < 4; r++) acc[mi][ni][r] = 0.f;

    load_tile(0, 0);

    const int NIT = KDIM / 32;
    for (int it = 0; it < NIT; it++) {
        const int buf = it & 1;
        CP_WAIT0();
        __syncthreads();
        if (it + 1 < NIT) load_tile(it + 1, buf ^ 1);

        const uint32_t base = smb + buf * BUFSZ;
        #pragma unroll
        for (int ks = 0; ks < 32; ks += 16) {
            uint32_t ah[4][4], bh[4][2], bl[4][2];
            #pragma unroll
            for (int mi = 0; mi < 4; mi++) {
                uint32_t adr = base + OFF_A +
                    (uint32_t)((wm + mi * 16 + (lane & 15)) * LDA +
                               ks + ((lane >> 4) << 3)) * 2;
                ldsm_x4(ah[mi][0], ah[mi][1], ah[mi][2], ah[mi][3], adr);
            }
            #pragma unroll
            for (int ni = 0; ni < 4; ni++) {
                uint32_t adr = base +
                    (uint32_t)((ks + (lane & 15)) * LDB + wn + ni * 8) * 2;
                ldsm_x2t(bh[ni][0], bh[ni][1], adr + OFF_BHI);
                ldsm_x2t(bl[ni][0], bl[ni][1], adr + OFF_BLO);
            }
            #pragma unroll
            for (int mi = 0; mi < 4; mi++)
                #pragma unroll
                for (int ni = 0; ni < 4; ni++) {
                    mma16816h(acc[mi][ni], ah[mi], bh[ni]);
                    mma16816h(acc[mi][ni], ah[mi], bl[ni]);
                }
        }
        __syncthreads();
    }

    const int r = lane >> 2;
    const int c = (lane & 3) << 1;
    #pragma unroll
    for (int mi = 0; mi < 4; mi++) {
        const int m1 = m0 + wm + mi * 16 + r;
        #pragma unroll
        for (int ni = 0; ni < 4; ni++) {
            const int n = n0 + wn + ni * 8 + c;
            float2 bb = *reinterpret_cast<const float2*>(bias + n);
            float2 o0 = { acc[mi][ni][0] + bb.x, acc[mi][ni][1] + bb.y };
            float2 o1 = { acc[mi][ni][2] + bb.x, acc[mi][ni][3] + bb.y };
            *reinterpret_cast<float2*>(C + (size_t)m1 * KDIM + n)       = o0;
            *reinterpret_cast<float2*>(C + (size_t)(m1 + 8) * KDIM + n) = o1;
        }
    }
}

// ========== rope (halves, NEGATIVE rotation — verified) + fp16 cvt =========
#define ROPE_L2 0.2076205059304601f   // log2(10000)/64
__global__ __launch_bounds__(64) void rope_cvt_kernel(
    const float* __restrict__ Qf, const float* __restrict__ Kf,
    const float* __restrict__ Vf,
    __half* __restrict__ Qh, __half* __restrict__ Kh, __half* __restrict__ Vh)
{
    const int row = blockIdx.x;
    const int h   = blockIdx.y;
    const int i   = threadIdx.x;
    const int s   = row & (SEQL - 1);

    const float inv = exp2f(-ROPE_L2 * (float)i);
    float c, sn;
    sincosf((float)s * inv, &c, &sn);

    const size_t off = (size_t)row * DM + (size_t)h * HDIM + i;
    float q1 = Qf[off], q2 = Qf[off + 64];
    Qh[off]      = __float2half( q1 * c + q2 * sn);
    Qh[off + 64] = __float2half(-q1 * sn + q2 * c);
    float k1 = Kf[off], k2 = Kf[off + 64];
    Kh[off]      = __float2half( k1 * c + k2 * sn);
    Kh[off + 64] = __float2half(-k1 * sn + k2 * c);
    Vh[off]      = __float2half(Vf[off]);
    Vh[off + 64] = __float2half(Vf[off + 64]);
}

// ================= MMA flash attention (fp16 tensor cores) =================
// CTA: 64 queries x one (b,h); 4 warps x 16 query rows; 64-key tiles.
#define LDK 136
#define TILEB (64 * LDK * 2)          // 17408 B
#define AOFF_Q 0
#define AOFF_K TILEB
#define AOFF_V (2 * TILEB)
#define ASMEM  (3 * TILEB)            // 52224 B
#define LOG2E  1.4426950408889634f

__global__ __launch_bounds__(128) void swattn_mma_kernel(
    const __half* __restrict__ Qh, const __half* __restrict__ Kh,
    const __half* __restrict__ Vh, const float* __restrict__ kw,
    __half* __restrict__ Oh)
{
    extern __shared__ __align__(16) char sm[];
    const uint32_t smb = smem_u32(sm);
    const int tid  = threadIdx.x;
    const int lane = tid & 31;
    const int wid  = tid >> 5;
    const int bh   = blockIdx.y;
    const int b    = bh >> 4;
    const int h    = bh & 15;
    const int i0   = blockIdx.x * 64;
    const float scale2 = kw[h] * 0.08838834764831845f * LOG2E;

    const int g   = lane >> 2;        // fragment row-in-8
    const int tIG = lane & 3;
    const int rA  = i0 + wid * 16 + g;     // my row pair
    const int rB  = rA + 8;

    // ---- load Q tile (64 x 128 fp16) into smem ----
    {
        const __half* Qg = Qh + ((size_t)(b * SEQL + i0)) * DM + (size_t)h * HDIM;
        for (int idx = tid; idx < 64 * 16; idx += 128) {
            int r = idx >> 4, c = idx & 15;
            cpasync16(smb + AOFF_Q + (uint32_t)(r * LDK + c * 8) * 2,
                      Qg + (size_t)r * DM + c * 8);
        }
        CP_COMMIT();
    }

    float oacc[16][4];
    #pragma unroll
    for (int nd = 0; nd < 16; nd++)
        #pragma unroll
        for (int r = 0; r < 4; r++) oacc[nd][r] = 0.f;
    float mA = -1e30f, mB = -1e30f, lsA = 0.f, lsB = 0.f;

    int jt0 = i0 - WINDOW; if (jt0 < 0) jt0 = 0;
    for (int jt = jt0; jt <= i0; jt += 64) {
        // ---- load K/V tiles ----
        {
            const __half* Kg = Kh + ((size_t)(b * SEQL + jt)) * DM + (size_t)h * HDIM;
            const __half* Vg = Vh + ((size_t)(b * SEQL + jt)) * DM + (size_t)h * HDIM;
            for (int idx = tid; idx < 64 * 16; idx += 128) {
                int r = idx >> 4, c = idx & 15;
                uint32_t d = (uint32_t)(r * LDK + c * 8) * 2;
                cpasync16(smb + AOFF_K + d, Kg + (size_t)r * DM + c * 8);
                cpasync16(smb + AOFF_V + d, Vg + (size_t)r * DM + c * 8);
            }
            CP_COMMIT();
        }
        CP_WAIT0();
        __syncthreads();

        // ---- S = Q K^T  (warp: 16 rows x 64 keys) ----
        float sacc[8][4];
        #pragma unroll
        for (int nj = 0; nj < 8; nj++)
            #pragma unroll
            for (int r = 0; r < 4; r++) sacc[nj][r] = 0.f;
        #pragma unroll
        for (int kt = 0; kt < 8; kt++) {
            uint32_t aq[4];
            {
                uint32_t adr = smb + AOFF_Q +
                    (uint32_t)((wid * 16 + (lane & 15)) * LDK +
                               kt * 16 + ((lane >> 4) << 3)) * 2;
                ldsm_x4(aq[0], aq[1], aq[2], aq[3], adr);
            }
            #pragma unroll
            for (int nj = 0; nj < 8; nj++) {
                uint32_t bfr[2];
                uint32_t adr = smb + AOFF_K +
                    (uint32_t)((nj * 8 + (lane & 7)) * LDK +
                               kt * 16 + (((lane >> 3) & 1) << 3)) * 2;
                ldsm_x2(bfr[0], bfr[1], adr);
                mma16816h(sacc[nj], aq, bfr);
            }
        }

        // ---- mask + scale (exp2 domain) ----
        float p[8][4];
        #pragma unroll
        for (int nj = 0; nj < 8; nj++) {
            int j0 = jt + nj * 8 + 2 * tIG;
            int j1 = j0 + 1;
            p[nj][0] = (j0 <= rA && j0 >= rA - WINDOW) ? sacc[nj][0] * scale2 : -1e30f;
            p[nj][1] = (j1 <= rA && j1 >= rA - WINDOW) ? sacc[nj][1] * scale2 : -1e30f;
            p[nj][2] = (j0 <= rB && j0 >= rB - WINDOW) ? sacc[nj][2] * scale2 : -1e30f;
            p[nj][3] = (j1 <= rB && j1 >= rB - WINDOW) ? sacc[nj][3] * scale2 : -1e30f;
        }

        // ---- row max (thread-local then 4-lane butterfly) ----
        float tmA = -1e30f, tmB = -1e30f;
        #pragma unroll
        for (int nj = 0; nj < 8; nj++) {
            tmA = fmaxf(tmA, fmaxf(p[nj][0], p[nj][1]));
            tmB = fmaxf(tmB, fmaxf(p[nj][2], p[nj][3]));
        }
        #pragma unroll
        for (int off = 1; off <= 2; off <<= 1) {
            tmA = fmaxf(tmA, __shfl_xor_sync(0xffffffffu, tmA, off));
            tmB = fmaxf(tmB, __shfl_xor_sync(0xffffffffu, tmB, off));
        }
        float mnA = fmaxf(mA, tmA), mnB = fmaxf(mB, tmB);
        float alA = exp2f(mA - mnA), alB = exp2f(mB - mnB);

        // ---- p = 2^(s - m), row sums ----
        float rsA = 0.f, rsB = 0.f;
        #pragma unroll
        for (int nj = 0; nj < 8; nj++) {
            p[nj][0] = exp2f(p[nj][0] - mnA);
            p[nj][1] = exp2f(p[nj][1] - mnA);
            p[nj][2] = exp2f(p[nj][2] - mnB);
            p[nj][3] = exp2f(p[nj][3] - mnB);
            rsA += p[nj][0] + p[nj][1];
            rsB += p[nj][2] + p[nj][3];
        }
        #pragma unroll
        for (int off = 1; off <= 2; off <<= 1) {
            rsA += __shfl_xor_sync(0xffffffffu, rsA, off);
            rsB += __shfl_xor_sync(0xffffffffu, rsB, off);
        }
        lsA = lsA * alA + rsA;
        lsB = lsB * alB + rsB;
        mA = mnA; mB = mnB;

        // ---- rescale O ----
        #pragma unroll
        for (int nd = 0; nd < 16; nd++) {
            oacc[nd][0] *= alA; oacc[nd][1] *= alA;
            oacc[nd][2] *= alB; oacc[nd][3] *= alB;
        }

        // ---- O += P V ----
        #pragma unroll
        for (int kk = 0; kk < 4; kk++) {
            uint32_t ap[4];
            ap[0] = h2u(__floats2half2_rn(p[2*kk][0],   p[2*kk][1]));
            ap[1] = h2u(__floats2half2_rn(p[2*kk][2],   p[2*kk][3]));
            ap[2] = h2u(__floats2half2_rn(p[2*kk+1][0], p[2*kk+1][1]));
            ap[3] = h2u(__floats2half2_rn(p[2*kk+1][2], p[2*kk+1][3]));
            #pragma unroll
            for (int nd = 0; nd < 8; nd++) {
                uint32_t bv[4];
                uint32_t adr = smb + AOFF_V +
                    (uint32_t)((kk * 16 + (lane & 15)) * LDK +
                               nd * 16 + ((lane >> 4) << 3)) * 2;
                ldsm_x4t(bv[0], bv[1], bv[2], bv[3], adr);
                mma16816h(oacc[2*nd],     ap, bv);
                mma16816h(oacc[2*nd + 1], ap, bv + 2);
            }
        }
        __syncthreads();
    }

    // ---- epilogue: normalize + fp16 store ----
    const float ivA = 1.0f / lsA, ivB = 1.0f / lsB;
    __half* OgA = Oh + ((size_t)(b * SEQL + rA)) * DM + (size_t)h * HDIM;
    __half* OgB = Oh + ((size_t)(b * SEQL + rB)) * DM + (size_t)h * HDIM;
    #pragma unroll
    for (int nd = 0; nd < 16; nd++) {
        int col = nd * 8 + 2 * tIG;
        *reinterpret_cast<__half2*>(OgA + col) =
            __floats2half2_rn(oacc[nd][0] * ivA, oacc[nd][1] * ivA);
        *reinterpret_cast<__half2*>(OgB + col) =
            __floats2half2_rn(oacc[nd][2] * ivB, oacc[nd][3] * ivB);
    }
}

// =============================== launch ====================================
extern "C" void kernel_launch(void* const* d_in, const int* in_sizes, int n_in,
                              void* d_out, int out_size)
{
    const float* x = 0; const float* Ws[4] = {0,0,0,0};
    const float* bs[4] = {0,0,0,0}; const float* kww = 0;
    int nw = 0, nb = 0;
    for (int idx = 0; idx < n_in; idx++) {
        int sz = in_sizes[idx];
        const float* p = (const float*)d_in[idx];
        if      (sz == ROWS * HIDDEN) { if (!x) x = p; }
        else if (sz == HIDDEN * DM)   { if (nw < 4) Ws[nw++] = p; }
        else if (sz == DM)            { if (nb < 4) bs[nb++] = p; }
        else if (sz == NHEADS)        { if (!kww) kww = p; }
    }
    float* out = (float*)d_out;

    float *qp, *kp, *vp;
    __half *xh, *whi, *wlo, *qh, *kh, *vh, *ah;
    cudaGetSymbolAddress((void**)&qp,  s_Q);
    cudaGetSymbolAddress((void**)&kp,  s_K);
    cudaGetSymbolAddress((void**)&vp,  s_V);
    cudaGetSymbolAddress((void**)&xh,  g_xh);
    cudaGetSymbolAddress((void**)&whi, g_Whi);
    cudaGetSymbolAddress((void**)&wlo, g_Wlo);
    cudaGetSymbolAddress((void**)&qh,  g_Qh);
    cudaGetSymbolAddress((void**)&kh,  g_Kh);
    cudaGetSymbolAddress((void**)&vh,  g_Vh);
    cudaGetSymbolAddress((void**)&ah,  g_ah);

    cudaFuncSetAttribute(gemm_mma_kernel,
                         cudaFuncAttributeMaxDynamicSharedMemorySize, GSMEM);
    cudaFuncSetAttribute(swattn_mma_kernel,
                         cudaFuncAttributeMaxDynamicSharedMemorySize, ASMEM);

    // (1) conversions, one launch
    WPtrs wp; wp.p[0] = Ws[0]; wp.p[1] = Ws[1]; wp.p[2] = Ws[2]; wp.p[3] = Ws[3];
    prep_kernel<<<(WTOT + ROWS * HIDDEN) / 256, 256>>>(wp, x, whi, wlo, xh);

    // (2..4) QKV projections
    dim3 ggrid(KDIM / 128, ROWS / 128);
    gemm_mma_kernel<<<ggrid, 256, GSMEM>>>(xh,
        whi + 0 * (size_t)KDIM * KDIM, wlo + 0 * (size_t)KDIM * KDIM, bs[0], qp);
    gemm_mma_kernel<<<ggrid, 256, GSMEM>>>(xh,
        whi + 1 * (size_t)KDIM * KDIM, wlo + 1 * (size_t)KDIM * KDIM, bs[1], kp);
    gemm_mma_kernel<<<ggrid, 256, GSMEM>>>(xh,
        whi + 2 * (size_t)KDIM * KDIM, wlo + 2 * (size_t)KDIM * KDIM, bs[2], vp);

    // (5) rope + fp16 conversion
    dim3 rgrid(ROWS, NHEADS);
    rope_cvt_kernel<<<rgrid, 64>>>(qp, kp, vp, qh, kh, vh);

    // (6) MMA flash attention  (profiled launch under -s 5 -c 1)
    dim3 agrid(SEQL / 64, BATCHN * NHEADS);
    swattn_mma_kernel<<<agrid, 128, ASMEM>>>(qh, kh, vh, kww, ah);

    // (7) O projection
    gemm_mma_kernel<<<ggrid, 256, GSMEM>>>(ah,
        whi + 3 * (size_t)KDIM * KDIM, wlo + 3 * (size_t)KDIM * KDIM, bs[3], out);
}

// round 13
// speedup vs baseline: 3.8036x; 1.0084x over previous
#include <cuda_runtime.h>
#include <cuda_fp16.h>
#include <cstdint>
#include <string.h>
#include <math.h>

// Problem constants
#define HIDDEN 2048
#define NHEADS 16
#define HDIM   128
#define SEQL   2048
#define BATCHN 2
#define WINDOW 256
#define ROWS   (BATCHN * SEQL)   // 4096
#define DM     (NHEADS * HDIM)   // 2048
#define KDIM   2048

// -------------------- scratch (no allocations allowed) --------------------
__device__ __half g_xh[ROWS * HIDDEN];
__device__ __half g_Wh[4 * KDIM * KDIM];   // all four W as fp16, [w][K][N]
__device__ __half g_Qh[ROWS * DM];         // Q (GEMM out, then roped in-place)
__device__ __half g_Kh[ROWS * DM];         // K (GEMM out, then roped in-place)
__device__ __half g_Vh[ROWS * DM];         // V (GEMM out, used directly)
__device__ __half g_ah[ROWS * DM];         // attention out, fp16

// ======================= PTX helpers =======================================
__device__ __forceinline__ uint32_t smem_u32(const void* p) {
    uint32_t a;
    asm("{ .reg .u64 t; cvta.to.shared.u64 t, %1; cvt.u32.u64 %0, t; }"
        : "=r"(a) : "l"(p));
    return a;
}
__device__ __forceinline__ uint32_t h2u(__half2 v) {
    uint32_t u;
    memcpy(&u, &v, 4);
    return u;
}
__device__ __forceinline__ void ldsm_x4(uint32_t& r0, uint32_t& r1,
                                        uint32_t& r2, uint32_t& r3, uint32_t a) {
    asm volatile("ldmatrix.sync.aligned.m8n8.x4.shared.b16 {%0,%1,%2,%3}, [%4];"
                 : "=r"(r0), "=r"(r1), "=r"(r2), "=r"(r3) : "r"(a));
}
__device__ __forceinline__ void ldsm_x4t(uint32_t& r0, uint32_t& r1,
                                         uint32_t& r2, uint32_t& r3, uint32_t a) {
    asm volatile("ldmatrix.sync.aligned.m8n8.x4.trans.shared.b16 {%0,%1,%2,%3}, [%4];"
                 : "=r"(r0), "=r"(r1), "=r"(r2), "=r"(r3) : "r"(a));
}
__device__ __forceinline__ void ldsm_x2(uint32_t& r0, uint32_t& r1, uint32_t a) {
    asm volatile("ldmatrix.sync.aligned.m8n8.x2.shared.b16 {%0,%1}, [%2];"
                 : "=r"(r0), "=r"(r1) : "r"(a));
}
__device__ __forceinline__ void ldsm_x2t(uint32_t& r0, uint32_t& r1, uint32_t a) {
    asm volatile("ldmatrix.sync.aligned.m8n8.x2.trans.shared.b16 {%0,%1}, [%2];"
                 : "=r"(r0), "=r"(r1) : "r"(a));
}
__device__ __forceinline__ void mma16816h(float* d, const uint32_t* a,
                                          const uint32_t* b) {
    asm volatile(
        "mma.sync.aligned.m16n8k16.row.col.f32.f16.f16.f32 "
        "{%0,%1,%2,%3}, {%4,%5,%6,%7}, {%8,%9}, {%0,%1,%2,%3};"
        : "+f"(d[0]), "+f"(d[1]), "+f"(d[2]), "+f"(d[3])
        : "r"(a[0]), "r"(a[1]), "r"(a[2]), "r"(a[3]), "r"(b[0]), "r"(b[1]));
}
__device__ __forceinline__ void cpasync16(uint32_t dst, const void* src) {
    asm volatile("cp.async.cg.shared.global [%0], [%1], 16;"
                 :: "r"(dst), "l"(src));
}
#define CP_COMMIT() asm volatile("cp.async.commit_group;" ::: "memory")
#define CP_WAIT0()  asm volatile("cp.async.wait_group 0;" ::: "memory")

// ================= prep: W -> fp16, x -> fp16 (one launch) =================
struct WPtrs { const float* p[4]; };
#define WTOT (4u * KDIM * KDIM)   // 16777216
__global__ void prep_kernel(WPtrs w, const float* __restrict__ x,
                            __half* __restrict__ wh, __half* __restrict__ xh)
{
    size_t gid = (size_t)blockIdx.x * blockDim.x + threadIdx.x;
    if (gid < WTOT) {
        wh[gid] = __float2half(w.p[gid >> 22][gid & 0x3FFFFFu]);
    } else {
        size_t i = gid - WTOT;
        xh[i] = __float2half(x[i]);
    }
}

// ============ fp16 tensor-core GEMM: C = A@W + bias (1-term, batched) ======
// CTA 128x128, K-chunk 32, 8 warps (2x4), warp tile 64x32.
// grid.z selects (B, bias, C) — QKV fused in one launch.
#define LDA 40
#define LDB 136
#define SZ_A (128 * LDA * 2)          // 10240 B
#define SZ_B (32 * LDB * 2)           // 8704 B
#define OFF_A   0
#define OFF_B   SZ_A
#define BUFSZ   (SZ_A + SZ_B)         // 18944 B
#define GSMEM   (2 * BUFSZ)           // 37888 B

struct GemmBatch { const __half* B[3]; const float* bias[3]; void* C[3]; };

template <typename TOut>
__global__ __launch_bounds__(256) void gemm_mma_kernel(
    const __half* __restrict__ A, GemmBatch g)
{
    extern __shared__ __align__(16) char sm[];
    const uint32_t smb = smem_u32(sm);
    const __half* __restrict__ B    = g.B[blockIdx.z];
    const float*  __restrict__ bias = g.bias[blockIdx.z];
    TOut* __restrict__ C            = (TOut*)g.C[blockIdx.z];

    const int tid  = threadIdx.x;
    const int lane = tid & 31;
    const int wid  = tid >> 5;
    const int wm   = (wid >> 2) * 64;
    const int wn   = (wid & 3) * 32;
    const int m0   = blockIdx.y * 128;
    const int n0   = blockIdx.x * 128;

    const int am  = tid >> 2;
    const int ak  = (tid & 3) << 3;
    const int bk  = tid >> 4;
    const int bn  = (tid & 15) << 3;

    auto load_tile = [&](int it, int buf) {
        const int k0 = it * 32;
        const uint32_t base = smb + buf * BUFSZ;
        #pragma unroll
        for (int j = 0; j < 2; j++) {
            int m = am + j * 64;
            cpasync16(base + OFF_A + (uint32_t)(m * LDA + ak) * 2,
                      A + (size_t)(m0 + m) * KDIM + k0 + ak);
            int kb = bk + j * 16;
            cpasync16(base + OFF_B + (uint32_t)(kb * LDB + bn) * 2,
                      B + (size_t)(k0 + kb) * KDIM + n0 + bn);
        }
        CP_COMMIT();
    };

    float acc[4][4][4];
    #pragma unroll
    for (int mi = 0; mi < 4; mi++)
        #pragma unroll
        for (int ni = 0; ni < 4; ni++)
            #pragma unroll
            for (int r = 0; r < 4; r++) acc[mi][ni][r] = 0.f;

    load_tile(0, 0);

    const int NIT = KDIM / 32;
    for (int it = 0; it < NIT; it++) {
        const int buf = it & 1;
        CP_WAIT0();
        __syncthreads();
        if (it + 1 < NIT) load_tile(it + 1, buf ^ 1);

        const uint32_t base = smb + buf * BUFSZ;
        #pragma unroll
        for (int ks = 0; ks < 32; ks += 16) {
            uint32_t ah[4][4], bh[4][2];
            #pragma unroll
            for (int mi = 0; mi < 4; mi++) {
                uint32_t adr = base + OFF_A +
                    (uint32_t)((wm + mi * 16 + (lane & 15)) * LDA +
                               ks + ((lane >> 4) << 3)) * 2;
                ldsm_x4(ah[mi][0], ah[mi][1], ah[mi][2], ah[mi][3], adr);
            }
            #pragma unroll
            for (int ni = 0; ni < 4; ni++) {
                uint32_t adr = base + OFF_B +
                    (uint32_t)((ks + (lane & 15)) * LDB + wn + ni * 8) * 2;
                ldsm_x2t(bh[ni][0], bh[ni][1], adr);
            }
            #pragma unroll
            for (int mi = 0; mi < 4; mi++)
                #pragma unroll
                for (int ni = 0; ni < 4; ni++)
                    mma16816h(acc[mi][ni], ah[mi], bh[ni]);
        }
        __syncthreads();
    }

    const int r = lane >> 2;
    const int c = (lane & 3) << 1;
    #pragma unroll
    for (int mi = 0; mi < 4; mi++) {
        const int m1 = m0 + wm + mi * 16 + r;
        #pragma unroll
        for (int ni = 0; ni < 4; ni++) {
            const int n = n0 + wn + ni * 8 + c;
            float2 bb = *reinterpret_cast<const float2*>(bias + n);
            float v00 = acc[mi][ni][0] + bb.x, v01 = acc[mi][ni][1] + bb.y;
            float v10 = acc[mi][ni][2] + bb.x, v11 = acc[mi][ni][3] + bb.y;
            if constexpr (sizeof(TOut) == 2) {
                *reinterpret_cast<__half2*>(C + (size_t)m1 * KDIM + n) =
                    __floats2half2_rn(v00, v01);
                *reinterpret_cast<__half2*>(C + (size_t)(m1 + 8) * KDIM + n) =
                    __floats2half2_rn(v10, v11);
            } else {
                float2 o0 = {v00, v01}, o1 = {v10, v11};
                *reinterpret_cast<float2*>((float*)C + (size_t)m1 * KDIM + n)       = o0;
                *reinterpret_cast<float2*>((float*)C + (size_t)(m1 + 8) * KDIM + n) = o1;
            }
        }
    }
}

// ====== RoPE in-place on fp16 Q/K (halves pairing, NEGATIVE rotation) ======
#define ROPE_L2 0.2076205059304601f   // log2(10000)/64
__global__ __launch_bounds__(64) void rope_h_kernel(
    __half* __restrict__ Q, __half* __restrict__ K)
{
    const int row = blockIdx.x;
    const int h   = blockIdx.y;
    const int i   = threadIdx.x;
    const int s   = row & (SEQL - 1);

    const float inv = exp2f(-ROPE_L2 * (float)i);
    float c, sn;
    sincosf((float)s * inv, &c, &sn);

    const size_t off = (size_t)row * DM + (size_t)h * HDIM + i;
    float q1 = __half2float(Q[off]), q2 = __half2float(Q[off + 64]);
    Q[off]      = __float2half( q1 * c + q2 * sn);
    Q[off + 64] = __float2half(-q1 * sn + q2 * c);
    float k1 = __half2float(K[off]), k2 = __half2float(K[off + 64]);
    K[off]      = __float2half( k1 * c + k2 * sn);
    K[off + 64] = __float2half(-k1 * sn + k2 * c);
}

// ================= MMA flash attention (fp16 tensor cores) =================
// CTA: 64 queries x one (b,h); 4 warps x 16 query rows; 64-key tiles.
#define LDK 136
#define TILEB (64 * LDK * 2)          // 17408 B
#define AOFF_Q 0
#define AOFF_K TILEB
#define AOFF_V (2 * TILEB)
#define ASMEM  (3 * TILEB)            // 52224 B
#define LOG2E  1.4426950408889634f

__global__ __launch_bounds__(128) void swattn_mma_kernel(
    const __half* __restrict__ Qh, const __half* __restrict__ Kh,
    const __half* __restrict__ Vh, const float* __restrict__ kw,
    __half* __restrict__ Oh)
{
    extern __shared__ __align__(16) char sm[];
    const uint32_t smb = smem_u32(sm);
    const int tid  = threadIdx.x;
    const int lane = tid & 31;
    const int wid  = tid >> 5;
    const int bh   = blockIdx.y;
    const int b    = bh >> 4;
    const int h    = bh & 15;
    const int i0   = blockIdx.x * 64;
    const float scale2 = kw[h] * 0.08838834764831845f * LOG2E;

    const int g   = lane >> 2;
    const int tIG = lane & 3;
    const int rA  = i0 + wid * 16 + g;
    const int rB  = rA + 8;

    {
        const __half* Qg = Qh + ((size_t)(b * SEQL + i0)) * DM + (size_t)h * HDIM;
        for (int idx = tid; idx < 64 * 16; idx += 128) {
            int r = idx >> 4, c = idx & 15;
            cpasync16(smb + AOFF_Q + (uint32_t)(r * LDK + c * 8) * 2,
                      Qg + (size_t)r * DM + c * 8);
        }
        CP_COMMIT();
    }

    float oacc[16][4];
    #pragma unroll
    for (int nd = 0; nd < 16; nd++)
        #pragma unroll
        for (int r = 0; r < 4; r++) oacc[nd][r] = 0.f;
    float mA = -1e30f, mB = -1e30f, lsA = 0.f, lsB = 0.f;

    int jt0 = i0 - WINDOW; if (jt0 < 0) jt0 = 0;
    for (int jt = jt0; jt <= i0; jt += 64) {
        {
            const __half* Kg = Kh + ((size_t)(b * SEQL + jt)) * DM + (size_t)h * HDIM;
            const __half* Vg = Vh + ((size_t)(b * SEQL + jt)) * DM + (size_t)h * HDIM;
            for (int idx = tid; idx < 64 * 16; idx += 128) {
                int r = idx >> 4, c = idx & 15;
                uint32_t d = (uint32_t)(r * LDK + c * 8) * 2;
                cpasync16(smb + AOFF_K + d, Kg + (size_t)r * DM + c * 8);
                cpasync16(smb + AOFF_V + d, Vg + (size_t)r * DM + c * 8);
            }
            CP_COMMIT();
        }
        CP_WAIT0();
        __syncthreads();

        float sacc[8][4];
        #pragma unroll
        for (int nj = 0; nj < 8; nj++)
            #pragma unroll
            for (int r = 0; r < 4; r++) sacc[nj][r] = 0.f;
        #pragma unroll
        for (int kt = 0; kt < 8; kt++) {
            uint32_t aq[4];
            {
                uint32_t adr = smb + AOFF_Q +
                    (uint32_t)((wid * 16 + (lane & 15)) * LDK +
                               kt * 16 + ((lane >> 4) << 3)) * 2;
                ldsm_x4(aq[0], aq[1], aq[2], aq[3], adr);
            }
            #pragma unroll
            for (int nj = 0; nj < 8; nj++) {
                uint32_t bfr[2];
                uint32_t adr = smb + AOFF_K +
                    (uint32_t)((nj * 8 + (lane & 7)) * LDK +
                               kt * 16 + (((lane >> 3) & 1) << 3)) * 2;
                ldsm_x2(bfr[0], bfr[1], adr);
                mma16816h(sacc[nj], aq, bfr);
            }
        }

        float p[8][4];
        #pragma unroll
        for (int nj = 0; nj < 8; nj++) {
            int j0 = jt + nj * 8 + 2 * tIG;
            int j1 = j0 + 1;
            p[nj][0] = (j0 <= rA && j0 >= rA - WINDOW) ? sacc[nj][0] * scale2 : -1e30f;
            p[nj][1] = (j1 <= rA && j1 >= rA - WINDOW) ? sacc[nj][1] * scale2 : -1e30f;
            p[nj][2] = (j0 <= rB && j0 >= rB - WINDOW) ? sacc[nj][2] * scale2 : -1e30f;
            p[nj][3] = (j1 <= rB && j1 >= rB - WINDOW) ? sacc[nj][3] * scale2 : -1e30f;
        }

        float tmA = -1e30f, tmB = -1e30f;
        #pragma unroll
        for (int nj = 0; nj < 8; nj++) {
            tmA = fmaxf(tmA, fmaxf(p[nj][0], p[nj][1]));
            tmB = fmaxf(tmB, fmaxf(p[nj][2], p[nj][3]));
        }
        #pragma unroll
        for (int off = 1; off <= 2; off <<= 1) {
            tmA = fmaxf(tmA, __shfl_xor_sync(0xffffffffu, tmA, off));
            tmB = fmaxf(tmB, __shfl_xor_sync(0xffffffffu, tmB, off));
        }
        float mnA = fmaxf(mA, tmA), mnB = fmaxf(mB, tmB);
        float alA = exp2f(mA - mnA), alB = exp2f(mB - mnB);

        float rsA = 0.f, rsB = 0.f;
        #pragma unroll
        for (int nj = 0; nj < 8; nj++) {
            p[nj][0] = exp2f(p[nj][0] - mnA);
            p[nj][1] = exp2f(p[nj][1] - mnA);
            p[nj][2] = exp2f(p[nj][2] - mnB);
            p[nj][3] = exp2f(p[nj][3] - mnB);
            rsA += p[nj][0] + p[nj][1];
            rsB += p[nj][2] + p[nj][3];
        }
        #pragma unroll
        for (int off = 1; off <= 2; off <<= 1) {
            rsA += __shfl_xor_sync(0xffffffffu, rsA, off);
            rsB += __shfl_xor_sync(0xffffffffu, rsB, off);
        }
        lsA = lsA * alA + rsA;
        lsB = lsB * alB + rsB;
        mA = mnA; mB = mnB;

        #pragma unroll
        for (int nd = 0; nd < 16; nd++) {
            oacc[nd][0] *= alA; oacc[nd][1] *= alA;
            oacc[nd][2] *= alB; oacc[nd][3] *= alB;
        }

        #pragma unroll
        for (int kk = 0; kk < 4; kk++) {
            uint32_t ap[4];
            ap[0] = h2u(__floats2half2_rn(p[2*kk][0],   p[2*kk][1]));
            ap[1] = h2u(__floats2half2_rn(p[2*kk][2],   p[2*kk][3]));
            ap[2] = h2u(__floats2half2_rn(p[2*kk+1][0], p[2*kk+1][1]));
            ap[3] = h2u(__floats2half2_rn(p[2*kk+1][2], p[2*kk+1][3]));
            #pragma unroll
            for (int nd = 0; nd < 8; nd++) {
                uint32_t bv[4];
                uint32_t adr = smb + AOFF_V +
                    (uint32_t)((kk * 16 + (lane & 15)) * LDK +
                               nd * 16 + ((lane >> 4) << 3)) * 2;
                ldsm_x4t(bv[0], bv[1], bv[2], bv[3], adr);
                mma16816h(oacc[2*nd],     ap, bv);
                mma16816h(oacc[2*nd + 1], ap, bv + 2);
            }
        }
        __syncthreads();
    }

    const float ivA = 1.0f / lsA, ivB = 1.0f / lsB;
    __half* OgA = Oh + ((size_t)(b * SEQL + rA)) * DM + (size_t)h * HDIM;
    __half* OgB = Oh + ((size_t)(b * SEQL + rB)) * DM + (size_t)h * HDIM;
    #pragma unroll
    for (int nd = 0; nd < 16; nd++) {
        int col = nd * 8 + 2 * tIG;
        *reinterpret_cast<__half2*>(OgA + col) =
            __floats2half2_rn(oacc[nd][0] * ivA, oacc[nd][1] * ivA);
        *reinterpret_cast<__half2*>(OgB + col) =
            __floats2half2_rn(oacc[nd][2] * ivB, oacc[nd][3] * ivB);
    }
}

// =============================== launch ====================================
extern "C" void kernel_launch(void* const* d_in, const int* in_sizes, int n_in,
                              void* d_out, int out_size)
{
    const float* x = 0; const float* Ws[4] = {0,0,0,0};
    const float* bs[4] = {0,0,0,0}; const float* kww = 0;
    int nw = 0, nb = 0;
    for (int idx = 0; idx < n_in; idx++) {
        int sz = in_sizes[idx];
        const float* p = (const float*)d_in[idx];
        if      (sz == ROWS * HIDDEN) { if (!x) x = p; }
        else if (sz == HIDDEN * DM)   { if (nw < 4) Ws[nw++] = p; }
        else if (sz == DM)            { if (nb < 4) bs[nb++] = p; }
        else if (sz == NHEADS)        { if (!kww) kww = p; }
    }
    float* out = (float*)d_out;

    __half *xh, *wh, *qh, *kh, *vh, *ah;
    cudaGetSymbolAddress((void**)&xh, g_xh);
    cudaGetSymbolAddress((void**)&wh, g_Wh);
    cudaGetSymbolAddress((void**)&qh, g_Qh);
    cudaGetSymbolAddress((void**)&kh, g_Kh);
    cudaGetSymbolAddress((void**)&vh, g_Vh);
    cudaGetSymbolAddress((void**)&ah, g_ah);

    cudaFuncSetAttribute(gemm_mma_kernel<__half>,
                         cudaFuncAttributeMaxDynamicSharedMemorySize, GSMEM);
    cudaFuncSetAttribute(gemm_mma_kernel<float>,
                         cudaFuncAttributeMaxDynamicSharedMemorySize, GSMEM);
    cudaFuncSetAttribute(swattn_mma_kernel,
                         cudaFuncAttributeMaxDynamicSharedMemorySize, ASMEM);

    // (1) conversions
    WPtrs wp; wp.p[0] = Ws[0]; wp.p[1] = Ws[1]; wp.p[2] = Ws[2]; wp.p[3] = Ws[3];
    prep_kernel<<<(WTOT + ROWS * HIDDEN) / 256, 256>>>(wp, x, wh, xh);

    // (2) QKV fused, fp16 outputs
    GemmBatch gq;
    gq.B[0] = wh + 0 * (size_t)KDIM * KDIM; gq.bias[0] = bs[0]; gq.C[0] = qh;
    gq.B[1] = wh + 1 * (size_t)KDIM * KDIM; gq.bias[1] = bs[1]; gq.C[1] = kh;
    gq.B[2] = wh + 2 * (size_t)KDIM * KDIM; gq.bias[2] = bs[2]; gq.C[2] = vh;
    dim3 g3(KDIM / 128, ROWS / 128, 3);
    gemm_mma_kernel<__half><<<g3, 256, GSMEM>>>(xh, gq);

    // (3) rope in-place on fp16 Q/K
    dim3 rgrid(ROWS, NHEADS);
    rope_h_kernel<<<rgrid, 64>>>(qh, kh);

    // (4) MMA flash attention
    dim3 agrid(SEQL / 64, BATCHN * NHEADS);
    swattn_mma_kernel<<<agrid, 128, ASMEM>>>(qh, kh, vh, kww, ah);

    // (5) O projection, fp32 output
    GemmBatch go;
    go.B[0] = wh + 3 * (size_t)KDIM * KDIM; go.bias[0] = bs[3]; go.C[0] = out;
    go.B[1] = go.B[0]; go.bias[1] = bs[3]; go.C[1] = out;   // unused lanes
    go.B[2] = go.B[0]; go.bias[2] = bs[3]; go.C[2] = out;
    dim3 g1(KDIM / 128, ROWS / 128, 1);
    gemm_mma_kernel<float><<<g1, 256, GSMEM>>>(ah, go);
}

// round 16
// speedup vs baseline: 5.8492x; 1.5378x over previous
#include <cuda_runtime.h>
#include <cuda_fp16.h>
#include <cstdint>
#include <string.h>
#include <math.h>

// Problem constants
#define HIDDEN 2048
#define NHEADS 16
#define HDIM   128
#define SEQL   2048
#define BATCHN 2
#define WINDOW 256
#define ROWS   (BATCHN * SEQL)   // 4096
#define DM     (NHEADS * HDIM)   // 2048
#define KDIM   2048

// -------------------- scratch (no allocations allowed) --------------------
__device__ __half g_xh[ROWS * HIDDEN];
__device__ __half g_Wh[4 * KDIM * KDIM];   // all four W as fp16, [w][K][N]
__device__ __half g_Qh[ROWS * DM];
__device__ __half g_Kh[ROWS * DM];
__device__ __half g_Vh[ROWS * DM];
__device__ __half g_ah[ROWS * DM];

// ======================= PTX helpers =======================================
__device__ __forceinline__ uint32_t smem_u32(const void* p) {
    uint32_t a;
    asm("{ .reg .u64 t; cvta.to.shared.u64 t, %1; cvt.u32.u64 %0, t; }"
        : "=r"(a) : "l"(p));
    return a;
}
__device__ __forceinline__ uint32_t h2u(__half2 v) {
    uint32_t u;
    memcpy(&u, &v, 4);
    return u;
}
__device__ __forceinline__ void ldsm_x4(uint32_t& r0, uint32_t& r1,
                                        uint32_t& r2, uint32_t& r3, uint32_t a) {
    asm volatile("ldmatrix.sync.aligned.m8n8.x4.shared.b16 {%0,%1,%2,%3}, [%4];"
                 : "=r"(r0), "=r"(r1), "=r"(r2), "=r"(r3) : "r"(a));
}
__device__ __forceinline__ void ldsm_x4t(uint32_t& r0, uint32_t& r1,
                                         uint32_t& r2, uint32_t& r3, uint32_t a) {
    asm volatile("ldmatrix.sync.aligned.m8n8.x4.trans.shared.b16 {%0,%1,%2,%3}, [%4];"
                 : "=r"(r0), "=r"(r1), "=r"(r2), "=r"(r3) : "r"(a));
}
__device__ __forceinline__ void ldsm_x2(uint32_t& r0, uint32_t& r1, uint32_t a) {
    asm volatile("ldmatrix.sync.aligned.m8n8.x2.shared.b16 {%0,%1}, [%2];"
                 : "=r"(r0), "=r"(r1) : "r"(a));
}
__device__ __forceinline__ void ldsm_x2t(uint32_t& r0, uint32_t& r1, uint32_t a) {
    asm volatile("ldmatrix.sync.aligned.m8n8.x2.trans.shared.b16 {%0,%1}, [%2];"
                 : "=r"(r0), "=r"(r1) : "r"(a));
}
__device__ __forceinline__ void mma16816h(float* d, const uint32_t* a,
                                          const uint32_t* b) {
    asm volatile(
        "mma.sync.aligned.m16n8k16.row.col.f32.f16.f16.f32 "
        "{%0,%1,%2,%3}, {%4,%5,%6,%7}, {%8,%9}, {%0,%1,%2,%3};"
        : "+f"(d[0]), "+f"(d[1]), "+f"(d[2]), "+f"(d[3])
        : "r"(a[0]), "r"(a[1]), "r"(a[2]), "r"(a[3]), "r"(b[0]), "r"(b[1]));
}
__device__ __forceinline__ void cpasync16(uint32_t dst, const void* src) {
    asm volatile("cp.async.cg.shared.global [%0], [%1], 16;"
                 :: "r"(dst), "l"(src));
}
#define CP_COMMIT() asm volatile("cp.async.commit_group;" ::: "memory")
#define CP_WAIT0()  asm volatile("cp.async.wait_group 0;" ::: "memory")
#define CP_WAIT2()  asm volatile("cp.async.wait_group 2;" ::: "memory")

// ================= prep: W -> fp16, x -> fp16 (one launch) =================
struct WPtrs { const float* p[4]; };
#define WTOT (4u * KDIM * KDIM)
__global__ void prep_kernel(WPtrs w, const float* __restrict__ x,
                            __half* __restrict__ wh, __half* __restrict__ xh)
{
    size_t gid = (size_t)blockIdx.x * blockDim.x + threadIdx.x;
    if (gid < WTOT) {
        wh[gid] = __float2half(w.p[gid >> 22][gid & 0x3FFFFFu]);
    } else {
        size_t i = gid - WTOT;
        xh[i] = __float2half(x[i]);
    }
}

// ======== fp16 tensor-core GEMM, 4-stage cp.async pipeline, batched ========
// CTA 128x128, K-chunk 32, 8 warps (2x4), warp tile 64x32; grid.z = batch.
#define LDA 40
#define LDB 136
#define SZ_A (128 * LDA * 2)
#define SZ_B (32 * LDB * 2)
#define OFF_A   0
#define OFF_B   SZ_A
#define BUFSZ   (SZ_A + SZ_B)         // 18944 B
#define STAGES  4
#define GSMEM   (STAGES * BUFSZ)      // 75776 B

struct GemmBatch { const __half* B[3]; const float* bias[3]; void* C[3]; };

template <typename TOut>
__global__ __launch_bounds__(256) void gemm_mma_kernel(
    const __half* __restrict__ A, GemmBatch g)
{
    extern __shared__ __align__(16) char sm[];
    const uint32_t smb = smem_u32(sm);
    const __half* __restrict__ B    = g.B[blockIdx.z];
    const float*  __restrict__ bias = g.bias[blockIdx.z];
    TOut* __restrict__ C            = (TOut*)g.C[blockIdx.z];

    const int tid  = threadIdx.x;
    const int lane = tid & 31;
    const int wid  = tid >> 5;
    const int wm   = (wid >> 2) * 64;
    const int wn   = (wid & 3) * 32;
    const int m0   = blockIdx.y * 128;
    const int n0   = blockIdx.x * 128;

    const int am  = tid >> 2;
    const int ak  = (tid & 3) << 3;
    const int bk  = tid >> 4;
    const int bn  = (tid & 15) << 3;

    auto load_tile = [&](int it, int buf) {
        const int k0 = it * 32;
        const uint32_t base = smb + buf * BUFSZ;
        #pragma unroll
        for (int j = 0; j < 2; j++) {
            int m = am + j * 64;
            cpasync16(base + OFF_A + (uint32_t)(m * LDA + ak) * 2,
                      A + (size_t)(m0 + m) * KDIM + k0 + ak);
            int kb = bk + j * 16;
            cpasync16(base + OFF_B + (uint32_t)(kb * LDB + bn) * 2,
                      B + (size_t)(k0 + kb) * KDIM + n0 + bn);
        }
        CP_COMMIT();
    };

    float acc[4][4][4];
    #pragma unroll
    for (int mi = 0; mi < 4; mi++)
        #pragma unroll
        for (int ni = 0; ni < 4; ni++)
            #pragma unroll
            for (int r = 0; r < 4; r++) acc[mi][ni][r] = 0.f;

    // prologue: fill 3 of 4 stages
    load_tile(0, 0);
    load_tile(1, 1);
    load_tile(2, 2);

    const int NIT = KDIM / 32;   // 64
    for (int it = 0; it < NIT; it++) {
        CP_WAIT2();              // <=2 groups pending -> stage it resident
        __syncthreads();
        if (it + STAGES - 1 < NIT) load_tile(it + STAGES - 1, (it + STAGES - 1) & 3);

        const uint32_t base = smb + (it & 3) * BUFSZ;
        #pragma unroll
        for (int ks = 0; ks < 32; ks += 16) {
            uint32_t ah[4][4], bh[4][2];
            #pragma unroll
            for (int mi = 0; mi < 4; mi++) {
                uint32_t adr = base + OFF_A +
                    (uint32_t)((wm + mi * 16 + (lane & 15)) * LDA +
                               ks + ((lane >> 4) << 3)) * 2;
                ldsm_x4(ah[mi][0], ah[mi][1], ah[mi][2], ah[mi][3], adr);
            }
            #pragma unroll
            for (int ni = 0; ni < 4; ni++) {
                uint32_t adr = base + OFF_B +
                    (uint32_t)((ks + (lane & 15)) * LDB + wn + ni * 8) * 2;
                ldsm_x2t(bh[ni][0], bh[ni][1], adr);
            }
            #pragma unroll
            for (int mi = 0; mi < 4; mi++)
                #pragma unroll
                for (int ni = 0; ni < 4; ni++)
                    mma16816h(acc[mi][ni], ah[mi], bh[ni]);
        }
    }

    const int r = lane >> 2;
    const int c = (lane & 3) << 1;
    #pragma unroll
    for (int mi = 0; mi < 4; mi++) {
        const int m1 = m0 + wm + mi * 16 + r;
        #pragma unroll
        for (int ni = 0; ni < 4; ni++) {
            const int n = n0 + wn + ni * 8 + c;
            float2 bb = *reinterpret_cast<const float2*>(bias + n);
            float v00 = acc[mi][ni][0] + bb.x, v01 = acc[mi][ni][1] + bb.y;
            float v10 = acc[mi][ni][2] + bb.x, v11 = acc[mi][ni][3] + bb.y;
            if constexpr (sizeof(TOut) == 2) {
                *reinterpret_cast<__half2*>(C + (size_t)m1 * KDIM + n) =
                    __floats2half2_rn(v00, v01);
                *reinterpret_cast<__half2*>(C + (size_t)(m1 + 8) * KDIM + n) =
                    __floats2half2_rn(v10, v11);
            } else {
                float2 o0 = {v00, v01}, o1 = {v10, v11};
                *reinterpret_cast<float2*>((float*)C + (size_t)m1 * KDIM + n)       = o0;
                *reinterpret_cast<float2*>((float*)C + (size_t)(m1 + 8) * KDIM + n) = o1;
            }
        }
    }
}

// ====== RoPE in-place on fp16 Q/K (halves pairing, NEGATIVE rotation) ======
#define ROPE_L2 0.2076205059304601f
__global__ __launch_bounds__(64) void rope_h_kernel(
    __half* __restrict__ Q, __half* __restrict__ K)
{
    const int row = blockIdx.x;
    const int h   = blockIdx.y;
    const int i   = threadIdx.x;
    const int s   = row & (SEQL - 1);

    const float inv = exp2f(-ROPE_L2 * (float)i);
    float c, sn;
    sincosf((float)s * inv, &c, &sn);

    const size_t off = (size_t)row * DM + (size_t)h * HDIM + i;
    float q1 = __half2float(Q[off]), q2 = __half2float(Q[off + 64]);
    Q[off]      = __float2half( q1 * c + q2 * sn);
    Q[off + 64] = __float2half(-q1 * sn + q2 * c);
    float k1 = __half2float(K[off]), k2 = __half2float(K[off + 64]);
    K[off]      = __float2half( k1 * c + k2 * sn);
    K[off + 64] = __float2half(-k1 * sn + k2 * c);
}

// ========= MMA flash attention (fp16), double-buffered K/V tiles ===========
#define LDK 136
#define TILEB (64 * LDK * 2)          // 17408 B
#define AOFF_Q 0
#define ASMEM  (5 * TILEB)            // Q + 2x(K,V) = 87040 B
#define LOG2E  1.4426950408889634f

__global__ __launch_bounds__(128) void swattn_mma_kernel(
    const __half* __restrict__ Qh, const __half* __restrict__ Kh,
    const __half* __restrict__ Vh, const float* __restrict__ kw,
    __half* __restrict__ Oh)
{
    extern __shared__ __align__(16) char sm[];
    const uint32_t smb = smem_u32(sm);
    const int tid  = threadIdx.x;
    const int lane = tid & 31;
    const int wid  = tid >> 5;
    const int bh   = blockIdx.y;
    const int b    = bh >> 4;
    const int h    = bh & 15;
    const int i0   = blockIdx.x * 64;
    const float scale2 = kw[h] * 0.08838834764831845f * LOG2E;

    const int g   = lane >> 2;
    const int tIG = lane & 3;
    const int rA  = i0 + wid * 16 + g;
    const int rB  = rA + 8;

    auto koff = [&](int buf) { return (uint32_t)(TILEB + buf * 2 * TILEB); };
    auto voff = [&](int buf) { return (uint32_t)(TILEB + buf * 2 * TILEB + TILEB); };

    auto load_kv = [&](int jt, int buf) {
        const __half* Kg = Kh + ((size_t)(b * SEQL + jt)) * DM + (size_t)h * HDIM;
        const __half* Vg = Vh + ((size_t)(b * SEQL + jt)) * DM + (size_t)h * HDIM;
        for (int idx = tid; idx < 64 * 16; idx += 128) {
            int r = idx >> 4, c = idx & 15;
            uint32_t d = (uint32_t)(r * LDK + c * 8) * 2;
            cpasync16(smb + koff(buf) + d, Kg + (size_t)r * DM + c * 8);
            cpasync16(smb + voff(buf) + d, Vg + (size_t)r * DM + c * 8);
        }
        CP_COMMIT();
    };

    // prologue: Q + first K/V tile (one group)
    int jt0 = i0 - WINDOW; if (jt0 < 0) jt0 = 0;
    {
        const __half* Qg = Qh + ((size_t)(b * SEQL + i0)) * DM + (size_t)h * HDIM;
        for (int idx = tid; idx < 64 * 16; idx += 128) {
            int r = idx >> 4, c = idx & 15;
            cpasync16(smb + AOFF_Q + (uint32_t)(r * LDK + c * 8) * 2,
                      Qg + (size_t)r * DM + c * 8);
        }
        load_kv(jt0, 0);
    }

    float oacc[16][4];
    #pragma unroll
    for (int nd = 0; nd < 16; nd++)
        #pragma unroll
        for (int r = 0; r < 4; r++) oacc[nd][r] = 0.f;
    float mA = -1e30f, mB = -1e30f, lsA = 0.f, lsB = 0.f;

    const int nt = (i0 - jt0) / 64 + 1;
    for (int n = 0; n < nt; n++) {
        const int jt  = jt0 + n * 64;
        const int buf = n & 1;
        CP_WAIT0();
        __syncthreads();
        if (n + 1 < nt) load_kv(jt + 64, buf ^ 1);

        float sacc[8][4];
        #pragma unroll
        for (int nj = 0; nj < 8; nj++)
            #pragma unroll
            for (int r = 0; r < 4; r++) sacc[nj][r] = 0.f;
        #pragma unroll
        for (int kt = 0; kt < 8; kt++) {
            uint32_t aq[4];
            {
                uint32_t adr = smb + AOFF_Q +
                    (uint32_t)((wid * 16 + (lane & 15)) * LDK +
                               kt * 16 + ((lane >> 4) << 3)) * 2;
                ldsm_x4(aq[0], aq[1], aq[2], aq[3], adr);
            }
            #pragma unroll
            for (int nj = 0; nj < 8; nj++) {
                uint32_t bfr[2];
                uint32_t adr = smb + koff(buf) +
                    (uint32_t)((nj * 8 + (lane & 7)) * LDK +
                               kt * 16 + (((lane >> 3) & 1) << 3)) * 2;
                ldsm_x2(bfr[0], bfr[1], adr);
                mma16816h(sacc[nj], aq, bfr);
            }
        }

        float p[8][4];
        #pragma unroll
        for (int nj = 0; nj < 8; nj++) {
            int j0 = jt + nj * 8 + 2 * tIG;
            int j1 = j0 + 1;
            p[nj][0] = (j0 <= rA && j0 >= rA - WINDOW) ? sacc[nj][0] * scale2 : -1e30f;
            p[nj][1] = (j1 <= rA && j1 >= rA - WINDOW) ? sacc[nj][1] * scale2 : -1e30f;
            p[nj][2] = (j0 <= rB && j0 >= rB - WINDOW) ? sacc[nj][2] * scale2 : -1e30f;
            p[nj][3] = (j1 <= rB && j1 >= rB - WINDOW) ? sacc[nj][3] * scale2 : -1e30f;
        }

        float tmA = -1e30f, tmB = -1e30f;
        #pragma unroll
        for (int nj = 0; nj < 8; nj++) {
            tmA = fmaxf(tmA, fmaxf(p[nj][0], p[nj][1]));
            tmB = fmaxf(tmB, fmaxf(p[nj][2], p[nj][3]));
        }
        #pragma unroll
        for (int off = 1; off <= 2; off <<= 1) {
            tmA = fmaxf(tmA, __shfl_xor_sync(0xffffffffu, tmA, off));
            tmB = fmaxf(tmB, __shfl_xor_sync(0xffffffffu, tmB, off));
        }
        float mnA = fmaxf(mA, tmA), mnB = fmaxf(mB, tmB);
        float alA = exp2f(mA - mnA), alB = exp2f(mB - mnB);

        float rsA = 0.f, rsB = 0.f;
        #pragma unroll
        for (int nj = 0; nj < 8; nj++) {
            p[nj][0] = exp2f(p[nj][0] - mnA);
            p[nj][1] = exp2f(p[nj][1] - mnA);
            p[nj][2] = exp2f(p[nj][2] - mnB);
            p[nj][3] = exp2f(p[nj][3] - mnB);
            rsA += p[nj][0] + p[nj][1];
            rsB += p[nj][2] + p[nj][3];
        }
        #pragma unroll
        for (int off = 1; off <= 2; off <<= 1) {
            rsA += __shfl_xor_sync(0xffffffffu, rsA, off);
            rsB += __shfl_xor_sync(0xffffffffu, rsB, off);
        }
        lsA = lsA * alA + rsA;
        lsB = lsB * alB + rsB;
        mA = mnA; mB = mnB;

        #pragma unroll
        for (int nd = 0; nd < 16; nd++) {
            oacc[nd][0] *= alA; oacc[nd][1] *= alA;
            oacc[nd][2] *= alB; oacc[nd][3] *= alB;
        }

        #pragma unroll
        for (int kk = 0; kk < 4; kk++) {
            uint32_t ap[4];
            ap[0] = h2u(__floats2half2_rn(p[2*kk][0],   p[2*kk][1]));
            ap[1] = h2u(__floats2half2_rn(p[2*kk][2],   p[2*kk][3]));
            ap[2] = h2u(__floats2half2_rn(p[2*kk+1][0], p[2*kk+1][1]));
            ap[3] = h2u(__floats2half2_rn(p[2*kk+1][2], p[2*kk+1][3]));
            #pragma unroll
            for (int nd = 0; nd < 8; nd++) {
                uint32_t bv[4];
                uint32_t adr = smb + voff(buf) +
                    (uint32_t)((kk * 16 + (lane & 15)) * LDK +
                               nd * 16 + ((lane >> 4) << 3)) * 2;
                ldsm_x4t(bv[0], bv[1], bv[2], bv[3], adr);
                mma16816h(oacc[2*nd],     ap, bv);
                mma16816h(oacc[2*nd + 1], ap, bv + 2);
            }
        }
    }

    const float ivA = 1.0f / lsA, ivB = 1.0f / lsB;
    __half* OgA = Oh + ((size_t)(b * SEQL + rA)) * DM + (size_t)h * HDIM;
    __half* OgB = Oh + ((size_t)(b * SEQL + rB)) * DM + (size_t)h * HDIM;
    #pragma unroll
    for (int nd = 0; nd < 16; nd++) {
        int col = nd * 8 + 2 * tIG;
        *reinterpret_cast<__half2*>(OgA + col) =
            __floats2half2_rn(oacc[nd][0] * ivA, oacc[nd][1] * ivA);
        *reinterpret_cast<__half2*>(OgB + col) =
            __floats2half2_rn(oacc[nd][2] * ivB, oacc[nd][3] * ivB);
    }
}

// =============================== launch ====================================
extern "C" void kernel_launch(void* const* d_in, const int* in_sizes, int n_in,
                              void* d_out, int out_size)
{
    const float* x = 0; const float* Ws[4] = {0,0,0,0};
    const float* bs[4] = {0,0,0,0}; const float* kww = 0;
    int nw = 0, nb = 0;
    for (int idx = 0; idx < n_in; idx++) {
        int sz = in_sizes[idx];
        const float* p = (const float*)d_in[idx];
        if      (sz == ROWS * HIDDEN) { if (!x) x = p; }
        else if (sz == HIDDEN * DM)   { if (nw < 4) Ws[nw++] = p; }
        else if (sz == DM)            { if (nb < 4) bs[nb++] = p; }
        else if (sz == NHEADS)        { if (!kww) kww = p; }
    }
    float* out = (float*)d_out;

    __half *xh, *wh, *qh, *kh, *vh, *ah;
    cudaGetSymbolAddress((void**)&xh, g_xh);
    cudaGetSymbolAddress((void**)&wh, g_Wh);
    cudaGetSymbolAddress((void**)&qh, g_Qh);
    cudaGetSymbolAddress((void**)&kh, g_Kh);
    cudaGetSymbolAddress((void**)&vh, g_Vh);
    cudaGetSymbolAddress((void**)&ah, g_ah);

    cudaFuncSetAttribute(gemm_mma_kernel<__half>,
                         cudaFuncAttributeMaxDynamicSharedMemorySize, GSMEM);
    cudaFuncSetAttribute(gemm_mma_kernel<float>,
                         cudaFuncAttributeMaxDynamicSharedMemorySize, GSMEM);
    cudaFuncSetAttribute(swattn_mma_kernel,
                         cudaFuncAttributeMaxDynamicSharedMemorySize, ASMEM);

    // (1) conversions
    WPtrs wp; wp.p[0] = Ws[0]; wp.p[1] = Ws[1]; wp.p[2] = Ws[2]; wp.p[3] = Ws[3];
    prep_kernel<<<(WTOT + ROWS * HIDDEN) / 256, 256>>>(wp, x, wh, xh);

    // (2) QKV fused, fp16 outputs
    GemmBatch gq;
    gq.B[0] = wh + 0 * (size_t)KDIM * KDIM; gq.bias[0] = bs[0]; gq.C[0] = qh;
    gq.B[1] = wh + 1 * (size_t)KDIM * KDIM; gq.bias[1] = bs[1]; gq.C[1] = kh;
    gq.B[2] = wh + 2 * (size_t)KDIM * KDIM; gq.bias[2] = bs[2]; gq.C[2] = vh;
    dim3 g3(KDIM / 128, ROWS / 128, 3);
    gemm_mma_kernel<__half><<<g3, 256, GSMEM>>>(xh, gq);

    // (3) rope in-place on fp16 Q/K
    dim3 rgrid(ROWS, NHEADS);
    rope_h_kernel<<<rgrid, 64>>>(qh, kh);

    // (4) MMA flash attention
    dim3 agrid(SEQL / 64, BATCHN * NHEADS);
    swattn_mma_kernel<<<agrid, 128, ASMEM>>>(qh, kh, vh, kww, ah);

    // (5) O projection, fp32 output
    GemmBatch go;
    go.B[0] = wh + 3 * (size_t)KDIM * KDIM; go.bias[0] = bs[3]; go.C[0] = out;
    go.B[1] = go.B[0]; go.bias[1] = bs[3]; go.C[1] = out;
    go.B[2] = go.B[0]; go.bias[2] = bs[3]; go.C[2] = out;
    dim3 g1(KDIM / 128, ROWS / 128, 1);
    gemm_mma_kernel<float><<<g1, 256, GSMEM>>>(ah, go);
}